// round 10
// baseline (speedup 1.0000x reference)
#include <cuda_runtime.h>
#include <cuda_bf16.h>
#include <float.h>

#define NN   100000
#define NE   1600000
#define IND  128
#define HIDD 256
#define NG   256
#define SMX_C 8

// ---------------- static device scratch (allocation-free rule) ----------------
__device__ float g_m[NN * IND];                  // relu(x @ W_pool + b_pool)
__device__ float g_h3[NN * HIDD];
__device__ float g_final[NG * HIDD];
__device__ int   g_start[NG + 1];

// pre-split bf16 hi/lo activations
__device__ __align__(256) unsigned short g_x_hi[NN * IND],   g_x_lo[NN * IND];
__device__ __align__(256) unsigned short g_nb_hi[NN * IND],  g_nb_lo[NN * IND];
__device__ __align__(256) unsigned short g_h1_hi[NN * HIDD], g_h1_lo[NN * HIDD];
__device__ __align__(256) unsigned short g_h2_hi[NN * HIDD], g_h2_lo[NN * HIDD];

// pre-split transposed weights [n][k]
__device__ __align__(256) unsigned short g_wpT_hi[IND * IND],   g_wpT_lo[IND * IND];
__device__ __align__(256) unsigned short g_wsT_hi[HIDD * IND],  g_wsT_lo[HIDD * IND];
__device__ __align__(256) unsigned short g_wnT_hi[HIDD * IND],  g_wnT_lo[HIDD * IND];
__device__ __align__(256) unsigned short g_w1T_hi[HIDD * HIDD], g_w1T_lo[HIDD * HIDD];
__device__ __align__(256) unsigned short g_w2T_hi[HIDD * HIDD], g_w2T_lo[HIDD * HIDD];

// CSR scratch
__device__ int g_deg[NN];
__device__ int g_cursor[NN];
__device__ int g_off[NN + 1];
__device__ int g_esrc[NE];
__device__ int g_bsum[128];

// softmax partials
__device__ float g_pmax[NG * SMX_C * HIDD];
__device__ float g_psum[NG * SMX_C * HIDD];

// ---------------- helpers ----------------
__device__ __forceinline__ void cvt_hl(float x, unsigned short& h, unsigned short& l) {
    __nv_bfloat16 bh = __float2bfloat16(x);
    __nv_bfloat16 bl = __float2bfloat16(x - __bfloat162float(bh));
    h = __bfloat16_as_ushort(bh);
    l = __bfloat16_as_ushort(bl);
}
__device__ __forceinline__ void mma16816(float* d, const unsigned* a, const unsigned* b) {
    asm volatile("mma.sync.aligned.m16n8k16.row.col.f32.bf16.bf16.f32 "
                 "{%0,%1,%2,%3}, {%4,%5,%6,%7}, {%8,%9}, {%0,%1,%2,%3};"
                 : "+f"(d[0]), "+f"(d[1]), "+f"(d[2]), "+f"(d[3])
                 : "r"(a[0]), "r"(a[1]), "r"(a[2]), "r"(a[3]),
                   "r"(b[0]), "r"(b[1]));
}
__device__ __forceinline__ void cpa16(void* dst, const void* src, int srcsize) {
    unsigned s = (unsigned)__cvta_generic_to_shared(dst);
    asm volatile("cp.async.cg.shared.global [%0], [%1], 16, %2;"
                 :: "r"(s), "l"(src), "r"(srcsize));
}
__device__ __forceinline__ void cpa_commit() {
    asm volatile("cp.async.commit_group;" ::: "memory");
}
__device__ __forceinline__ void cpa_wait0() {
    asm volatile("cp.async.wait_group 0;" ::: "memory");
}
__device__ __forceinline__ void cpa_wait1() {
    asm volatile("cp.async.wait_group 1;" ::: "memory");
}

// ---------------- graph ranges ----------------
__global__ void find_starts_kernel(const int* __restrict__ gid, int n, int G) {
    int g = blockIdx.x * blockDim.x + threadIdx.x;
    if (g > G) return;
    int lo = 0, hi = n;
    while (lo < hi) {
        int mid = (lo + hi) >> 1;
        if (gid[mid] < g) lo = mid + 1; else hi = mid;
    }
    g_start[g] = lo;
}

// ---------------- CSR build ----------------
__global__ void zero_deg_kernel(int n) {
    int i = blockIdx.x * blockDim.x + threadIdx.x;
    if (i < n) g_deg[i] = 0;
}
__global__ void hist_kernel(const int* __restrict__ dst, int ne) {
    int e = blockIdx.x * blockDim.x + threadIdx.x;
    if (e < ne) atomicAdd(&g_deg[dst[e]], 1);
}
__global__ void block_sums_kernel(int n) {
    __shared__ int sh[1024];
    int i = blockIdx.x * 1024 + threadIdx.x;
    sh[threadIdx.x] = (i < n) ? g_deg[i] : 0;
    __syncthreads();
    for (int s = 512; s > 0; s >>= 1) {
        if (threadIdx.x < s) sh[threadIdx.x] += sh[threadIdx.x + s];
        __syncthreads();
    }
    if (threadIdx.x == 0) g_bsum[blockIdx.x] = sh[0];
}
__global__ void scan_bsum_kernel(int nb, int n, int ne) {
    __shared__ int sh[128];
    int t = threadIdx.x;
    sh[t] = (t < nb) ? g_bsum[t] : 0;
    __syncthreads();
    for (int d = 1; d < 128; d <<= 1) {
        int v = (t >= d) ? sh[t - d] : 0;
        __syncthreads();
        sh[t] += v;
        __syncthreads();
    }
    if (t < nb) g_bsum[t] = (t == 0) ? 0 : sh[t - 1];
    if (t == 0) g_off[n] = ne;
}
__global__ void scan_block_kernel(int n) {
    __shared__ int sh[1024];
    int t = threadIdx.x;
    int i = blockIdx.x * 1024 + t;
    int v = (i < n) ? g_deg[i] : 0;
    sh[t] = v;
    __syncthreads();
    for (int d = 1; d < 1024; d <<= 1) {
        int u = (t >= d) ? sh[t - d] : 0;
        __syncthreads();
        sh[t] += u;
        __syncthreads();
    }
    if (i < n) {
        int off = g_bsum[blockIdx.x] + sh[t] - v;
        g_off[i] = off;
        g_cursor[i] = off;
    }
}
__global__ void scatter_kernel(const int* __restrict__ src, const int* __restrict__ dst, int ne) {
    int e = blockIdx.x * blockDim.x + threadIdx.x;
    if (e < ne) {
        int pos = atomicAdd(&g_cursor[dst[e]], 1);
        g_esrc[pos] = src[e];
    }
}

// ---------------- gather max: warp per dst node, writes bf16 hi/lo ----------
__global__ void gather_max_kernel(int n) {
    int warp = (blockIdx.x * blockDim.x + threadIdx.x) >> 5;
    if (warp >= n) return;
    int lane = threadIdx.x & 31;
    int c = lane * 4;
    int beg = g_off[warp], end = g_off[warp + 1];
    float4 acc = make_float4(0.f, 0.f, 0.f, 0.f);
    int j = beg;
    for (; j + 2 <= end; j += 2) {
        int s0 = __ldg(&g_esrc[j]);
        int s1 = __ldg(&g_esrc[j + 1]);
        float4 v0 = *reinterpret_cast<const float4*>(&g_m[s0 * IND + c]);
        float4 v1 = *reinterpret_cast<const float4*>(&g_m[s1 * IND + c]);
        acc.x = fmaxf(acc.x, fmaxf(v0.x, v1.x));
        acc.y = fmaxf(acc.y, fmaxf(v0.y, v1.y));
        acc.z = fmaxf(acc.z, fmaxf(v0.z, v1.z));
        acc.w = fmaxf(acc.w, fmaxf(v0.w, v1.w));
    }
    if (j < end) {
        int s0 = __ldg(&g_esrc[j]);
        float4 v0 = *reinterpret_cast<const float4*>(&g_m[s0 * IND + c]);
        acc.x = fmaxf(acc.x, v0.x);
        acc.y = fmaxf(acc.y, v0.y);
        acc.z = fmaxf(acc.z, v0.z);
        acc.w = fmaxf(acc.w, v0.w);
    }
    unsigned short h[4], l[4];
    cvt_hl(acc.x, h[0], l[0]); cvt_hl(acc.y, h[1], l[1]);
    cvt_hl(acc.z, h[2], l[2]); cvt_hl(acc.w, h[3], l[3]);
    uint2 hw, lw;
    hw.x = ((unsigned)h[1] << 16) | h[0];  hw.y = ((unsigned)h[3] << 16) | h[2];
    lw.x = ((unsigned)l[1] << 16) | l[0];  lw.y = ((unsigned)l[3] << 16) | l[2];
    *reinterpret_cast<uint2*>(&g_nb_hi[warp * IND + c]) = hw;
    *reinterpret_cast<uint2*>(&g_nb_lo[warp * IND + c]) = lw;
}

// ---------------- pre-split kernels ----------------
__global__ void split_rows4_kernel(const float* __restrict__ X,
                                   unsigned short* __restrict__ hi,
                                   unsigned short* __restrict__ lo, int n4) {
    int i = blockIdx.x * blockDim.x + threadIdx.x;
    if (i >= n4) return;
    float4 v = reinterpret_cast<const float4*>(X)[i];
    unsigned short h[4], l[4];
    cvt_hl(v.x, h[0], l[0]); cvt_hl(v.y, h[1], l[1]);
    cvt_hl(v.z, h[2], l[2]); cvt_hl(v.w, h[3], l[3]);
    uint2 hw, lw;
    hw.x = ((unsigned)h[1] << 16) | h[0];  hw.y = ((unsigned)h[3] << 16) | h[2];
    lw.x = ((unsigned)l[1] << 16) | l[0];  lw.y = ((unsigned)l[3] << 16) | l[2];
    *reinterpret_cast<uint2*>(&hi[i * 4]) = hw;
    *reinterpret_cast<uint2*>(&lo[i * 4]) = lw;
}
// W[K][N] -> hiT/loT [N][K]
__global__ void split_wT_kernel(const float* __restrict__ W, int K, int N,
                                unsigned short* __restrict__ hiT,
                                unsigned short* __restrict__ loT) {
    int idx = blockIdx.x * blockDim.x + threadIdx.x;
    if (idx >= K * N) return;
    int k = idx / N, n = idx % N;
    unsigned short h, l;
    cvt_hl(W[idx], h, l);
    hiT[n * K + k] = h;
    loT[n * K + k] = l;
}

// ---------------- pre-split bf16 tensor-core GEMM, cp.async double-buffered --
// C = relu(A1@B1 + A2@B2 + bias); A/B given as pre-split hi/lo (B transposed [n][k]).
// Block 128x128, 8 warps (4m x 2n), warp tile 32x64, BK=32, 2-stage pipeline.
// smem stage: A(hi,lo)[128][40] + B(hi,lo)[128][40] shorts = 20480 shorts.
template<int K1, int K2, int N, int SPLIT>
__global__ __launch_bounds__(256, 2)
void gemm_tc2(const unsigned short* __restrict__ A1h, const unsigned short* __restrict__ A1l,
              const unsigned short* __restrict__ A2h, const unsigned short* __restrict__ A2l,
              const unsigned short* __restrict__ B1hT, const unsigned short* __restrict__ B1lT,
              const unsigned short* __restrict__ B2hT, const unsigned short* __restrict__ B2lT,
              const float* __restrict__ bias,
              float* __restrict__ Cf,
              unsigned short* __restrict__ Chi, unsigned short* __restrict__ Clo,
              int M)
{
    constexpr int KT = K1 + K2;
    constexpr int T  = KT / 32;
    constexpr int STG = 20480;           // shorts per stage
    constexpr int PLANE = 5120;          // 128*40

    extern __shared__ unsigned short sm[];

    const int tid     = threadIdx.x;
    const int rowbase = blockIdx.x * 128;
    const int colbase = blockIdx.y * 128;

    const int lane = tid & 31;
    const int wid  = tid >> 5;
    const int wm   = (wid & 3) * 32;
    const int wn   = (wid >> 2) * 64;
    const int fr   = lane >> 2;
    const int fc   = (lane & 3) * 2;

    // staging coords
    const int a_row = tid >> 1;
    const int a_k0  = (tid & 1) * 16;
    const int a_grow = rowbase + a_row;
    const int a_sz   = (a_grow < M) ? 16 : 0;
    const int a_rowc = (a_grow < M) ? a_grow : 0;
    const int b_n    = tid & 127;
    const int b_kh   = tid >> 7;          // 0..1, 16-k halves

    float acc[2][8][4];
#pragma unroll
    for (int mt = 0; mt < 2; ++mt)
#pragma unroll
        for (int nt = 0; nt < 8; ++nt)
#pragma unroll
            for (int q = 0; q < 4; ++q) acc[mt][nt][q] = 0.f;

    auto issue_tile = [&](int t, int s) {
        const int kc = t * 32;
        unsigned short* Sa = sm + s * STG;
        unsigned short* Sb = Sa + 2 * PLANE;
        // A
        {
            int col = kc + a_k0;
            const unsigned short *gh, *gl;
            if constexpr (K2 == 0) {
                gh = A1h + (size_t)a_rowc * K1 + col;
                gl = A1l + (size_t)a_rowc * K1 + col;
            } else {
                if (col < K1) {
                    gh = A1h + (size_t)a_rowc * K1 + col;
                    gl = A1l + (size_t)a_rowc * K1 + col;
                } else {
                    gh = A2h + (size_t)a_rowc * K2 + (col - K1);
                    gl = A2l + (size_t)a_rowc * K2 + (col - K1);
                }
            }
            cpa16(&Sa[a_row * 40 + a_k0],             gh,     a_sz);
            cpa16(&Sa[a_row * 40 + a_k0 + 8],         gh + 8, a_sz);
            cpa16(&Sa[PLANE + a_row * 40 + a_k0],     gl,     a_sz);
            cpa16(&Sa[PLANE + a_row * 40 + a_k0 + 8], gl + 8, a_sz);
        }
        // B
        {
            int kb = kc + b_kh * 16;
            const unsigned short *gh, *gl;
            if constexpr (K2 == 0) {
                gh = B1hT + (size_t)(colbase + b_n) * K1 + kb;
                gl = B1lT + (size_t)(colbase + b_n) * K1 + kb;
            } else {
                if (kb < K1) {
                    gh = B1hT + (size_t)(colbase + b_n) * K1 + kb;
                    gl = B1lT + (size_t)(colbase + b_n) * K1 + kb;
                } else {
                    gh = B2hT + (size_t)(colbase + b_n) * K2 + (kb - K1);
                    gl = B2lT + (size_t)(colbase + b_n) * K2 + (kb - K1);
                }
            }
            cpa16(&Sb[b_n * 40 + b_kh * 16],             gh,     16);
            cpa16(&Sb[b_n * 40 + b_kh * 16 + 8],         gh + 8, 16);
            cpa16(&Sb[PLANE + b_n * 40 + b_kh * 16],     gl,     16);
            cpa16(&Sb[PLANE + b_n * 40 + b_kh * 16 + 8], gl + 8, 16);
        }
    };

    issue_tile(0, 0);
    cpa_commit();

#pragma unroll 1
    for (int t = 0; t < T; ++t) {
        if (t + 1 < T) {
            issue_tile(t + 1, (t + 1) & 1);
            cpa_commit();
            cpa_wait1();
        } else {
            cpa_wait0();
        }
        __syncthreads();

        const unsigned short* Sa = sm + (t & 1) * STG;
        const unsigned short* Sb = Sa + 2 * PLANE;
        const unsigned short* Ah = Sa;
        const unsigned short* Al = Sa + PLANE;
        const unsigned short* Bh = Sb;
        const unsigned short* Bl = Sb + PLANE;

#pragma unroll
        for (int kk = 0; kk < 32; kk += 16) {
            unsigned ah[2][4], al[2][4];
#pragma unroll
            for (int mt = 0; mt < 2; ++mt) {
                int r0 = wm + mt * 16 + fr;
                ah[mt][0] = *reinterpret_cast<const unsigned*>(&Ah[r0 * 40 + kk + fc]);
                ah[mt][1] = *reinterpret_cast<const unsigned*>(&Ah[(r0 + 8) * 40 + kk + fc]);
                ah[mt][2] = *reinterpret_cast<const unsigned*>(&Ah[r0 * 40 + kk + fc + 8]);
                ah[mt][3] = *reinterpret_cast<const unsigned*>(&Ah[(r0 + 8) * 40 + kk + fc + 8]);
                al[mt][0] = *reinterpret_cast<const unsigned*>(&Al[r0 * 40 + kk + fc]);
                al[mt][1] = *reinterpret_cast<const unsigned*>(&Al[(r0 + 8) * 40 + kk + fc]);
                al[mt][2] = *reinterpret_cast<const unsigned*>(&Al[r0 * 40 + kk + fc + 8]);
                al[mt][3] = *reinterpret_cast<const unsigned*>(&Al[(r0 + 8) * 40 + kk + fc + 8]);
            }
#pragma unroll
            for (int nt = 0; nt < 8; ++nt) {
                int nb = wn + nt * 8 + fr;
                unsigned bh[2], bl[2];
                bh[0] = *reinterpret_cast<const unsigned*>(&Bh[nb * 40 + kk + fc]);
                bh[1] = *reinterpret_cast<const unsigned*>(&Bh[nb * 40 + kk + fc + 8]);
                bl[0] = *reinterpret_cast<const unsigned*>(&Bl[nb * 40 + kk + fc]);
                bl[1] = *reinterpret_cast<const unsigned*>(&Bl[nb * 40 + kk + fc + 8]);
#pragma unroll
                for (int mt = 0; mt < 2; ++mt) {
                    mma16816(acc[mt][nt], ah[mt], bh);
                    mma16816(acc[mt][nt], ah[mt], bl);
                    mma16816(acc[mt][nt], al[mt], bh);
                }
            }
        }
        __syncthreads();
    }

    // ---- epilogue: bias + relu; fp32 or split-bf16 output ----
#pragma unroll
    for (int nt = 0; nt < 8; ++nt) {
        int cb = colbase + wn + nt * 8 + fc;
        float2 bi = *reinterpret_cast<const float2*>(&bias[cb]);
#pragma unroll
        for (int mt = 0; mt < 2; ++mt) {
            int r0 = rowbase + wm + mt * 16 + fr;
#pragma unroll
            for (int half = 0; half < 2; ++half) {
                int r = r0 + half * 8;
                if (r < M) {
                    float vx = fmaxf(acc[mt][nt][half * 2 + 0] + bi.x, 0.f);
                    float vy = fmaxf(acc[mt][nt][half * 2 + 1] + bi.y, 0.f);
                    if constexpr (SPLIT) {
                        unsigned short hx, lx, hy, ly;
                        cvt_hl(vx, hx, lx);
                        cvt_hl(vy, hy, ly);
                        *reinterpret_cast<ushort2*>(&Chi[(size_t)r * N + cb]) = make_ushort2(hx, hy);
                        *reinterpret_cast<ushort2*>(&Clo[(size_t)r * N + cb]) = make_ushort2(lx, ly);
                    } else {
                        *reinterpret_cast<float2*>(&Cf[(size_t)r * N + cb]) = make_float2(vx, vy);
                    }
                }
            }
        }
    }
}

// ---------------- chunked per-graph online softmax denominator ----------------
__global__ void softmax_partial_kernel()
{
    int b = blockIdx.x;
    int g = b >> 3, c = b & (SMX_C - 1);
    int s = g_start[g], e = g_start[g + 1];
    int len = e - s;
    int chunk = (len + SMX_C - 1) >> 3;
    int cs = s + c * chunk;
    int ce = min(cs + chunk, e);
    int f = threadIdx.x;
    const float* __restrict__ h = g_h3;

    float mx0 = -FLT_MAX, mx1 = -FLT_MAX;
    float s0 = 0.f, s1 = 0.f;
    int i = cs;
    for (; i + 2 <= ce; i += 2) {
        float v0 = h[(size_t)(i + 0) * HIDD + f];
        float v1 = h[(size_t)(i + 1) * HIDD + f];
        if (v0 > mx0) { s0 *= __expf(mx0 - v0); mx0 = v0; }
        s0 += __expf(v0 - mx0);
        if (v1 > mx1) { s1 *= __expf(mx1 - v1); mx1 = v1; }
        s1 += __expf(v1 - mx1);
    }
    for (; i < ce; ++i) {
        float v = h[(size_t)i * HIDD + f];
        if (v > mx0) { s0 *= __expf(mx0 - v); mx0 = v; }
        s0 += __expf(v - mx0);
    }
    float mx, sm;
    if (cs >= ce) { mx = -FLT_MAX; sm = 0.f; }
    else {
        mx = fmaxf(mx0, mx1);
        sm = s0 * __expf(mx0 - mx) + ((s1 > 0.f) ? s1 * __expf(mx1 - mx) : 0.f);
    }
    g_pmax[(size_t)b * HIDD + f] = mx;
    g_psum[(size_t)b * HIDD + f] = sm;
}

__global__ void softmax_combine_kernel()
{
    int g = blockIdx.x;
    int f = threadIdx.x;
    float Mx = -FLT_MAX;
#pragma unroll
    for (int c = 0; c < SMX_C; ++c)
        Mx = fmaxf(Mx, g_pmax[(size_t)(g * SMX_C + c) * HIDD + f]);
    float S = 0.f;
#pragma unroll
    for (int c = 0; c < SMX_C; ++c) {
        float pm = g_pmax[(size_t)(g * SMX_C + c) * HIDD + f];
        float ps = g_psum[(size_t)(g * SMX_C + c) * HIDD + f];
        if (ps > 0.f) S += ps * __expf(pm - Mx);
    }
    g_final[g * HIDD + f] = (g_start[g + 1] > g_start[g]) ? (1.0f / S) : 0.f;
}

// ---------------- tiny readout: out = final @ Wr + br ----------------
__global__ void readout_kernel(const float* __restrict__ Wr, const float* __restrict__ br,
                               float* __restrict__ out, int ngr)
{
    int t = blockIdx.x * blockDim.x + threadIdx.x;
    if (t < ngr * 2) {
        int g = t >> 1, o = t & 1;
        float acc = br[o];
        const float* fr = &g_final[g * HIDD];
#pragma unroll 8
        for (int f = 0; f < HIDD; ++f) acc = fmaf(fr[f], Wr[f * 2 + o], acc);
        out[t] = acc;
    }
}

// ---------------- launch ----------------
extern "C" void kernel_launch(void* const* d_in, const int* in_sizes, int n_in,
                              void* d_out, int out_size)
{
    const float* x       = (const float*)d_in[0];
    const float* W_pool  = (const float*)d_in[1];
    const float* b_pool  = (const float*)d_in[2];
    const float* W_self  = (const float*)d_in[3];
    const float* W_neigh = (const float*)d_in[4];
    const float* b_sage  = (const float*)d_in[5];
    const float* W1      = (const float*)d_in[6];
    const float* b1      = (const float*)d_in[7];
    const float* W2      = (const float*)d_in[8];
    const float* b2      = (const float*)d_in[9];
    const float* Wr      = (const float*)d_in[10];
    const float* br      = (const float*)d_in[11];
    const int*   src     = (const int*)d_in[12];
    const int*   dst     = (const int*)d_in[13];
    const int*   gid     = (const int*)d_in[14];
    float*       out     = (float*)d_out;

    const int M = in_sizes[0] / IND;   // 100000
    const int E = in_sizes[12];        // 1600000
    const int G = out_size / 2;        // 256

    const int SMEM_BYTES = 2 * 20480 * 2;   // 2 stages x 20480 shorts

    static bool attr_done = false;
    cudaFuncSetAttribute((const void*)gemm_tc2<128, 0, 128, 0>,
                         cudaFuncAttributeMaxDynamicSharedMemorySize, SMEM_BYTES);
    cudaFuncSetAttribute((const void*)gemm_tc2<128, 128, 256, 1>,
                         cudaFuncAttributeMaxDynamicSharedMemorySize, SMEM_BYTES);
    cudaFuncSetAttribute((const void*)gemm_tc2<256, 0, 256, 1>,
                         cudaFuncAttributeMaxDynamicSharedMemorySize, SMEM_BYTES);
    cudaFuncSetAttribute((const void*)gemm_tc2<256, 0, 256, 0>,
                         cudaFuncAttributeMaxDynamicSharedMemorySize, SMEM_BYTES);
    (void)attr_done;

    void *pm, *ph3;
    cudaGetSymbolAddress(&pm,  g_m);
    cudaGetSymbolAddress(&ph3, g_h3);
    void *pxh, *pxl, *pnh, *pnl, *p1h, *p1l, *p2h, *p2l;
    cudaGetSymbolAddress(&pxh, g_x_hi);  cudaGetSymbolAddress(&pxl, g_x_lo);
    cudaGetSymbolAddress(&pnh, g_nb_hi); cudaGetSymbolAddress(&pnl, g_nb_lo);
    cudaGetSymbolAddress(&p1h, g_h1_hi); cudaGetSymbolAddress(&p1l, g_h1_lo);
    cudaGetSymbolAddress(&p2h, g_h2_hi); cudaGetSymbolAddress(&p2l, g_h2_lo);
    void *wph, *wpl, *wsh, *wsl, *wnh, *wnl, *w1h, *w1l, *w2h, *w2l;
    cudaGetSymbolAddress(&wph, g_wpT_hi); cudaGetSymbolAddress(&wpl, g_wpT_lo);
    cudaGetSymbolAddress(&wsh, g_wsT_hi); cudaGetSymbolAddress(&wsl, g_wsT_lo);
    cudaGetSymbolAddress(&wnh, g_wnT_hi); cudaGetSymbolAddress(&wnl, g_wnT_lo);
    cudaGetSymbolAddress(&w1h, g_w1T_hi); cudaGetSymbolAddress(&w1l, g_w1T_lo);
    cudaGetSymbolAddress(&w2h, g_w2T_hi); cudaGetSymbolAddress(&w2l, g_w2T_lo);

    const int nb1024 = (M + 1023) / 1024;

    // stage 0a: graph ranges
    find_starts_kernel<<<1, 512>>>(gid, M, G);

    // stage 0b: weight splits + x split
    split_wT_kernel<<<(IND * IND + 255) / 256, 256>>>(W_pool, IND, IND,
        (unsigned short*)wph, (unsigned short*)wpl);
    split_wT_kernel<<<(IND * HIDD + 255) / 256, 256>>>(W_self, IND, HIDD,
        (unsigned short*)wsh, (unsigned short*)wsl);
    split_wT_kernel<<<(IND * HIDD + 255) / 256, 256>>>(W_neigh, IND, HIDD,
        (unsigned short*)wnh, (unsigned short*)wnl);
    split_wT_kernel<<<(HIDD * HIDD + 255) / 256, 256>>>(W1, HIDD, HIDD,
        (unsigned short*)w1h, (unsigned short*)w1l);
    split_wT_kernel<<<(HIDD * HIDD + 255) / 256, 256>>>(W2, HIDD, HIDD,
        (unsigned short*)w2h, (unsigned short*)w2l);
    split_rows4_kernel<<<(M * IND / 4 + 255) / 256, 256>>>(x,
        (unsigned short*)pxh, (unsigned short*)pxl, M * IND / 4);

    // stage 0c: CSR build
    zero_deg_kernel<<<(M + 255) / 256, 256>>>(M);
    hist_kernel<<<(E + 255) / 256, 256>>>(dst, E);
    block_sums_kernel<<<nb1024, 1024>>>(M);
    scan_bsum_kernel<<<1, 128>>>(nb1024, M, E);
    scan_block_kernel<<<nb1024, 1024>>>(M);
    scatter_kernel<<<(E + 255) / 256, 256>>>(src, dst, E);

    const int MB = (M + 127) / 128;

    // stage 1: m = relu(x @ W_pool + b_pool)  (fp32 out)
    gemm_tc2<128, 0, 128, 0><<<dim3(MB, 1), 256, SMEM_BYTES>>>(
        (const unsigned short*)pxh, (const unsigned short*)pxl, nullptr, nullptr,
        (const unsigned short*)wph, (const unsigned short*)wpl, nullptr, nullptr,
        b_pool, (float*)pm, nullptr, nullptr, M);

    // stage 2: neigh[d] = max over in-edges of m[src]  -> bf16 hi/lo
    gather_max_kernel<<<(M * 32 + 255) / 256, 256>>>(M);

    // stage 3: h1 = relu(x @ W_self + neigh @ W_neigh + b_sage)  (split out)
    gemm_tc2<128, 128, 256, 1><<<dim3(MB, 2), 256, SMEM_BYTES>>>(
        (const unsigned short*)pxh, (const unsigned short*)pxl,
        (const unsigned short*)pnh, (const unsigned short*)pnl,
        (const unsigned short*)wsh, (const unsigned short*)wsl,
        (const unsigned short*)wnh, (const unsigned short*)wnl,
        b_sage, nullptr, (unsigned short*)p1h, (unsigned short*)p1l, M);

    // stage 4: h2 = relu(h1 @ W1 + b1)  (split out)
    gemm_tc2<256, 0, 256, 1><<<dim3(MB, 2), 256, SMEM_BYTES>>>(
        (const unsigned short*)p1h, (const unsigned short*)p1l, nullptr, nullptr,
        (const unsigned short*)w1h, (const unsigned short*)w1l, nullptr, nullptr,
        b1, nullptr, (unsigned short*)p2h, (unsigned short*)p2l, M);

    // stage 5: h3 = relu(h2 @ W2 + b2)  (fp32 out)
    gemm_tc2<256, 0, 256, 0><<<dim3(MB, 2), 256, SMEM_BYTES>>>(
        (const unsigned short*)p2h, (const unsigned short*)p2l, nullptr, nullptr,
        (const unsigned short*)w2h, (const unsigned short*)w2l, nullptr, nullptr,
        b2, (float*)ph3, nullptr, nullptr, M);

    // stage 6: chunked per-graph softmax denominator -> final = 1/zsum
    softmax_partial_kernel<<<G * SMX_C, HIDD>>>();
    softmax_combine_kernel<<<G, HIDD>>>();

    // stage 7: out = final @ Wr + br
    readout_kernel<<<(G * 2 + 255) / 256, 256>>>(Wr, br, out, G);
}

// round 11
// speedup vs baseline: 1.0485x; 1.0485x over previous
#include <cuda_runtime.h>
#include <cuda_bf16.h>
#include <float.h>

#define NN   100000
#define NE   1600000
#define IND  128
#define HIDD 256
#define NG   256
#define SMX_C 8

// ---------------- static device scratch (allocation-free rule) ----------------
__device__ float g_m[NN * IND];        // relu(x @ W_pool + b_pool)
__device__ float g_neigh[NN * IND];    // segment_max over in-edges
__device__ float g_h1[NN * HIDD];
__device__ float g_h2[NN * HIDD];
__device__ float g_h3[NN * HIDD];
__device__ float g_final[NG * HIDD];   // 1/zsum per (graph, feature)
__device__ int   g_start[NG + 1];      // node range per graph (graph_id sorted)

// CSR scratch
__device__ int g_deg[NN];
__device__ int g_cursor[NN];
__device__ int g_off[NN + 1];
__device__ int g_esrc[NE];
__device__ int g_bsum[128];

// softmax partials
__device__ float g_pmax[NG * SMX_C * HIDD];
__device__ float g_psum[NG * SMX_C * HIDD];

// ---------------- FFMA-pipe exp (no MUFU): exp(x), x <= 0 -------------------
// exp(x) = 2^t, t = x*log2(e); t = i + f, f in [0,1); 2^f via degree-7 poly
// (Taylor in ln2, max rel err ~1e-6); 2^i via exponent-bit add. Clamp at -126.
__device__ __forceinline__ float fast_exp(float x) {
    float t = x * 1.4426950408889634f;
    t = fmaxf(t, -126.0f);
    float fi = floorf(t);
    float f  = t - fi;
    float p;
    p = fmaf(f, 1.5252733e-5f, 1.5403530e-4f);
    p = fmaf(f, p, 1.3333558e-3f);
    p = fmaf(f, p, 9.6181291e-3f);
    p = fmaf(f, p, 5.5504109e-2f);
    p = fmaf(f, p, 2.4022651e-1f);
    p = fmaf(f, p, 6.9314718e-1f);
    p = fmaf(f, p, 1.0f);
    int ei = (int)fi;
    float sc = __int_as_float((ei + 127) << 23);
    return p * sc;
}

// ---------------- graph ranges: gid sorted -> binary search ----------------
__global__ void find_starts_kernel(const int* __restrict__ gid, int n, int G) {
    int g = blockIdx.x * blockDim.x + threadIdx.x;
    if (g > G) return;
    int lo = 0, hi = n;
    while (lo < hi) {
        int mid = (lo + hi) >> 1;
        if (gid[mid] < g) lo = mid + 1; else hi = mid;
    }
    g_start[g] = lo;
}

// ---------------- CSR build ----------------
__global__ void zero_deg_kernel(int n) {
    int i = blockIdx.x * blockDim.x + threadIdx.x;
    if (i < n) g_deg[i] = 0;
}
__global__ void hist_kernel(const int* __restrict__ dst, int ne) {
    int e = blockIdx.x * blockDim.x + threadIdx.x;
    if (e < ne) atomicAdd(&g_deg[dst[e]], 1);
}
__global__ void block_sums_kernel(int n) {
    __shared__ int sh[1024];
    int i = blockIdx.x * 1024 + threadIdx.x;
    sh[threadIdx.x] = (i < n) ? g_deg[i] : 0;
    __syncthreads();
    for (int s = 512; s > 0; s >>= 1) {
        if (threadIdx.x < s) sh[threadIdx.x] += sh[threadIdx.x + s];
        __syncthreads();
    }
    if (threadIdx.x == 0) g_bsum[blockIdx.x] = sh[0];
}
__global__ void scan_bsum_kernel(int nb, int n, int ne) {
    __shared__ int sh[128];
    int t = threadIdx.x;
    sh[t] = (t < nb) ? g_bsum[t] : 0;
    __syncthreads();
    for (int d = 1; d < 128; d <<= 1) {
        int v = (t >= d) ? sh[t - d] : 0;
        __syncthreads();
        sh[t] += v;
        __syncthreads();
    }
    if (t < nb) g_bsum[t] = (t == 0) ? 0 : sh[t - 1];
    if (t == 0) g_off[n] = ne;
}
__global__ void scan_block_kernel(int n) {
    __shared__ int sh[1024];
    int t = threadIdx.x;
    int i = blockIdx.x * 1024 + t;
    int v = (i < n) ? g_deg[i] : 0;
    sh[t] = v;
    __syncthreads();
    for (int d = 1; d < 1024; d <<= 1) {
        int u = (t >= d) ? sh[t - d] : 0;
        __syncthreads();
        sh[t] += u;
        __syncthreads();
    }
    if (i < n) {
        int off = g_bsum[blockIdx.x] + sh[t] - v;
        g_off[i] = off;
        g_cursor[i] = off;
    }
}
__global__ void scatter_kernel(const int* __restrict__ src, const int* __restrict__ dst, int ne) {
    int e = blockIdx.x * blockDim.x + threadIdx.x;
    if (e < ne) {
        int pos = atomicAdd(&g_cursor[dst[e]], 1);
        g_esrc[pos] = src[e];
    }
}

// ---------------- gather max: warp per dst node, no atomics ----------------
__global__ void gather_max_kernel(int n) {
    int warp = (blockIdx.x * blockDim.x + threadIdx.x) >> 5;
    if (warp >= n) return;
    int lane = threadIdx.x & 31;
    int c = lane * 4;
    int beg = g_off[warp], end = g_off[warp + 1];
    float4 acc = make_float4(0.f, 0.f, 0.f, 0.f);
    int j = beg;
    for (; j + 2 <= end; j += 2) {
        int s0 = __ldg(&g_esrc[j]);
        int s1 = __ldg(&g_esrc[j + 1]);
        float4 v0 = *reinterpret_cast<const float4*>(&g_m[s0 * IND + c]);
        float4 v1 = *reinterpret_cast<const float4*>(&g_m[s1 * IND + c]);
        acc.x = fmaxf(acc.x, fmaxf(v0.x, v1.x));
        acc.y = fmaxf(acc.y, fmaxf(v0.y, v1.y));
        acc.z = fmaxf(acc.z, fmaxf(v0.z, v1.z));
        acc.w = fmaxf(acc.w, fmaxf(v0.w, v1.w));
    }
    if (j < end) {
        int s0 = __ldg(&g_esrc[j]);
        float4 v0 = *reinterpret_cast<const float4*>(&g_m[s0 * IND + c]);
        acc.x = fmaxf(acc.x, v0.x);
        acc.y = fmaxf(acc.y, v0.y);
        acc.z = fmaxf(acc.z, v0.z);
        acc.w = fmaxf(acc.w, v0.w);
    }
    *reinterpret_cast<float4*>(&g_neigh[warp * IND + c]) = acc;
}

// ---------------- bf16-split tensor-core GEMM + bias + relu (R9 proven) -----
__device__ __forceinline__ void cvt_hl(float x, unsigned short& h, unsigned short& l) {
    __nv_bfloat16 bh = __float2bfloat16(x);
    __nv_bfloat16 bl = __float2bfloat16(x - __bfloat162float(bh));
    h = __bfloat16_as_ushort(bh);
    l = __bfloat16_as_ushort(bl);
}

__device__ __forceinline__ void mma16816(float* d, const unsigned* a, const unsigned* b) {
    asm volatile("mma.sync.aligned.m16n8k16.row.col.f32.bf16.bf16.f32 "
                 "{%0,%1,%2,%3}, {%4,%5,%6,%7}, {%8,%9}, {%0,%1,%2,%3};"
                 : "+f"(d[0]), "+f"(d[1]), "+f"(d[2]), "+f"(d[3])
                 : "r"(a[0]), "r"(a[1]), "r"(a[2]), "r"(a[3]),
                   "r"(b[0]), "r"(b[1]));
}

template<int K1, int K2, int N>
__global__ __launch_bounds__(256, 2)
void gemm_tc(const float* __restrict__ A1, const float* __restrict__ A2,
             const float* __restrict__ B1, const float* __restrict__ B2,
             const float* __restrict__ bias, float* __restrict__ C, int M)
{
    constexpr int KT = K1 + K2;
    constexpr int T  = KT / 32;

    __shared__ unsigned short As[2][128][40];   // [hi/lo][row][k]
    __shared__ unsigned short Bs[2][128][40];   // [hi/lo][n][k]

    const int tid     = threadIdx.x;
    const int rowbase = blockIdx.x * 128;
    const int colbase = blockIdx.y * 128;

    const int lane = tid & 31;
    const int wid  = tid >> 5;
    const int wm   = (wid & 3) * 32;
    const int wn   = (wid >> 2) * 64;
    const int fr   = lane >> 2;
    const int fc   = (lane & 3) * 2;

    const int a_row = tid >> 1;
    const int a_k0  = (tid & 1) * 16;
    const int a_grow = rowbase + a_row;
    const bool a_ok  = a_grow < M;
    const int b_n   = tid & 127;
    const int b_kqb = tid >> 7;

    float acc[2][8][4];
#pragma unroll
    for (int mt = 0; mt < 2; ++mt)
#pragma unroll
        for (int nt = 0; nt < 8; ++nt)
#pragma unroll
            for (int q = 0; q < 4; ++q) acc[mt][nt][q] = 0.f;

#pragma unroll 1
    for (int t = 0; t < T; ++t) {
        const int kc = t * 32;
        __syncthreads();

        // ---- stage A (convert fp32 -> bf16 hi/lo) ----
        {
            const float* ap;
            if constexpr (K2 == 0) {
                ap = A1 + (size_t)a_grow * K1 + kc + a_k0;
            } else {
                ap = (kc < K1) ? A1 + (size_t)a_grow * K1 + kc + a_k0
                               : A2 + (size_t)a_grow * K2 + (kc - K1) + a_k0;
            }
#pragma unroll
            for (int i = 0; i < 4; ++i) {
                float4 v = a_ok ? *reinterpret_cast<const float4*>(ap + i * 4)
                                : make_float4(0.f, 0.f, 0.f, 0.f);
                unsigned short h[4], l[4];
                cvt_hl(v.x, h[0], l[0]); cvt_hl(v.y, h[1], l[1]);
                cvt_hl(v.z, h[2], l[2]); cvt_hl(v.w, h[3], l[3]);
                uint2 hw, lw;
                hw.x = ((unsigned)h[1] << 16) | h[0];
                hw.y = ((unsigned)h[3] << 16) | h[2];
                lw.x = ((unsigned)l[1] << 16) | l[0];
                lw.y = ((unsigned)l[3] << 16) | l[2];
                *reinterpret_cast<uint2*>(&As[0][a_row][a_k0 + i * 4]) = hw;
                *reinterpret_cast<uint2*>(&As[1][a_row][a_k0 + i * 4]) = lw;
            }
        }
        // ---- stage B transposed [n][k] ----
        {
#pragma unroll
            for (int it = 0; it < 4; ++it) {
                int kq = it * 2 + b_kqb;
                int kg = kc + kq * 4;
                const float* bp;
                if constexpr (K2 == 0) {
                    bp = B1 + (size_t)kg * N + colbase + b_n;
                } else {
                    bp = (kg < K1) ? B1 + (size_t)kg * N + colbase + b_n
                                   : B2 + (size_t)(kg - K1) * N + colbase + b_n;
                }
                unsigned short h[4], l[4];
#pragma unroll
                for (int i = 0; i < 4; ++i) cvt_hl(bp[(size_t)i * N], h[i], l[i]);
                uint2 hw, lw;
                hw.x = ((unsigned)h[1] << 16) | h[0];
                hw.y = ((unsigned)h[3] << 16) | h[2];
                lw.x = ((unsigned)l[1] << 16) | l[0];
                lw.y = ((unsigned)l[3] << 16) | l[2];
                *reinterpret_cast<uint2*>(&Bs[0][b_n][kq * 4]) = hw;
                *reinterpret_cast<uint2*>(&Bs[1][b_n][kq * 4]) = lw;
            }
        }
        __syncthreads();

        // ---- compute: two k16 steps ----
#pragma unroll
        for (int kk = 0; kk < 32; kk += 16) {
            unsigned ah[2][4], al[2][4];
#pragma unroll
            for (int mt = 0; mt < 2; ++mt) {
                int r0 = wm + mt * 16 + fr;
                ah[mt][0] = *reinterpret_cast<const unsigned*>(&As[0][r0    ][kk + fc    ]);
                ah[mt][1] = *reinterpret_cast<const unsigned*>(&As[0][r0 + 8][kk + fc    ]);
                ah[mt][2] = *reinterpret_cast<const unsigned*>(&As[0][r0    ][kk + fc + 8]);
                ah[mt][3] = *reinterpret_cast<const unsigned*>(&As[0][r0 + 8][kk + fc + 8]);
                al[mt][0] = *reinterpret_cast<const unsigned*>(&As[1][r0    ][kk + fc    ]);
                al[mt][1] = *reinterpret_cast<const unsigned*>(&As[1][r0 + 8][kk + fc    ]);
                al[mt][2] = *reinterpret_cast<const unsigned*>(&As[1][r0    ][kk + fc + 8]);
                al[mt][3] = *reinterpret_cast<const unsigned*>(&As[1][r0 + 8][kk + fc + 8]);
            }
#pragma unroll
            for (int nt = 0; nt < 8; ++nt) {
                int nb = wn + nt * 8 + fr;
                unsigned bh[2], bl[2];
                bh[0] = *reinterpret_cast<const unsigned*>(&Bs[0][nb][kk + fc    ]);
                bh[1] = *reinterpret_cast<const unsigned*>(&Bs[0][nb][kk + fc + 8]);
                bl[0] = *reinterpret_cast<const unsigned*>(&Bs[1][nb][kk + fc    ]);
                bl[1] = *reinterpret_cast<const unsigned*>(&Bs[1][nb][kk + fc + 8]);
#pragma unroll
                for (int mt = 0; mt < 2; ++mt) {
                    mma16816(acc[mt][nt], ah[mt], bh);
                    mma16816(acc[mt][nt], ah[mt], bl);
                    mma16816(acc[mt][nt], al[mt], bh);
                }
            }
        }
    }

    // ---- epilogue: bias + relu ----
#pragma unroll
    for (int nt = 0; nt < 8; ++nt) {
        int cb = colbase + wn + nt * 8 + fc;
        float2 bi = *reinterpret_cast<const float2*>(&bias[cb]);
#pragma unroll
        for (int mt = 0; mt < 2; ++mt) {
            int r0 = rowbase + wm + mt * 16 + fr;
            if (r0 < M) {
                float2 o;
                o.x = fmaxf(acc[mt][nt][0] + bi.x, 0.f);
                o.y = fmaxf(acc[mt][nt][1] + bi.y, 0.f);
                *reinterpret_cast<float2*>(&C[(size_t)r0 * N + cb]) = o;
            }
            if (r0 + 8 < M) {
                float2 o;
                o.x = fmaxf(acc[mt][nt][2] + bi.x, 0.f);
                o.y = fmaxf(acc[mt][nt][3] + bi.y, 0.f);
                *reinterpret_cast<float2*>(&C[(size_t)(r0 + 8) * N + cb]) = o;
            }
        }
    }
}

// ---------------- chunked per-graph softmax denominator (FFMA exp) ----------
__global__ void softmax_partial_kernel()
{
    int b = blockIdx.x;
    int g = b >> 3, c = b & (SMX_C - 1);
    int s = g_start[g], e = g_start[g + 1];
    int len = e - s;
    int chunk = (len + SMX_C - 1) >> 3;
    int cs = s + c * chunk;
    int ce = min(cs + chunk, e);
    int f = threadIdx.x;
    const float* __restrict__ h = g_h3;

    float mx0 = -FLT_MAX, mx1 = -FLT_MAX;
    float s0 = 0.f, s1 = 0.f;
    int i = cs;
    for (; i + 2 <= ce; i += 2) {
        float v0 = h[(size_t)(i + 0) * HIDD + f];
        float v1 = h[(size_t)(i + 1) * HIDD + f];
        if (v0 > mx0) { s0 *= fast_exp(mx0 - v0); mx0 = v0; }
        s0 += fast_exp(v0 - mx0);
        if (v1 > mx1) { s1 *= fast_exp(mx1 - v1); mx1 = v1; }
        s1 += fast_exp(v1 - mx1);
    }
    for (; i < ce; ++i) {
        float v = h[(size_t)i * HIDD + f];
        if (v > mx0) { s0 *= fast_exp(mx0 - v); mx0 = v; }
        s0 += fast_exp(v - mx0);
    }
    float mx, sm;
    if (cs >= ce) { mx = -FLT_MAX; sm = 0.f; }
    else {
        mx = fmaxf(mx0, mx1);
        sm = s0 * fast_exp(mx0 - mx) + ((s1 > 0.f) ? s1 * fast_exp(mx1 - mx) : 0.f);
    }
    g_pmax[(size_t)b * HIDD + f] = mx;
    g_psum[(size_t)b * HIDD + f] = sm;
}

__global__ void softmax_combine_kernel()
{
    int g = blockIdx.x;
    int f = threadIdx.x;
    float Mx = -FLT_MAX;
#pragma unroll
    for (int c = 0; c < SMX_C; ++c)
        Mx = fmaxf(Mx, g_pmax[(size_t)(g * SMX_C + c) * HIDD + f]);
    float S = 0.f;
#pragma unroll
    for (int c = 0; c < SMX_C; ++c) {
        float pm = g_pmax[(size_t)(g * SMX_C + c) * HIDD + f];
        float ps = g_psum[(size_t)(g * SMX_C + c) * HIDD + f];
        if (ps > 0.f) S += ps * fast_exp(pm - Mx);
    }
    g_final[g * HIDD + f] = (g_start[g + 1] > g_start[g]) ? (1.0f / S) : 0.f;
}

// ---------------- tiny readout: out = final @ Wr + br ----------------
__global__ void readout_kernel(const float* __restrict__ Wr, const float* __restrict__ br,
                               float* __restrict__ out, int ngr)
{
    int t = blockIdx.x * blockDim.x + threadIdx.x;
    if (t < ngr * 2) {
        int g = t >> 1, o = t & 1;
        float acc = br[o];
        const float* fr = &g_final[g * HIDD];
#pragma unroll 8
        for (int f = 0; f < HIDD; ++f) acc = fmaf(fr[f], Wr[f * 2 + o], acc);
        out[t] = acc;
    }
}

// ---------------- launch ----------------
extern "C" void kernel_launch(void* const* d_in, const int* in_sizes, int n_in,
                              void* d_out, int out_size)
{
    const float* x       = (const float*)d_in[0];
    const float* W_pool  = (const float*)d_in[1];
    const float* b_pool  = (const float*)d_in[2];
    const float* W_self  = (const float*)d_in[3];
    const float* W_neigh = (const float*)d_in[4];
    const float* b_sage  = (const float*)d_in[5];
    const float* W1      = (const float*)d_in[6];
    const float* b1      = (const float*)d_in[7];
    const float* W2      = (const float*)d_in[8];
    const float* b2      = (const float*)d_in[9];
    const float* Wr      = (const float*)d_in[10];
    const float* br      = (const float*)d_in[11];
    const int*   src     = (const int*)d_in[12];
    const int*   dst     = (const int*)d_in[13];
    const int*   gid     = (const int*)d_in[14];
    float*       out     = (float*)d_out;

    const int M = in_sizes[0] / IND;   // 100000
    const int E = in_sizes[12];        // 1600000
    const int G = out_size / 2;        // 256

    void *pm, *pn, *ph1, *ph2, *ph3;
    cudaGetSymbolAddress(&pm,  g_m);
    cudaGetSymbolAddress(&pn,  g_neigh);
    cudaGetSymbolAddress(&ph1, g_h1);
    cudaGetSymbolAddress(&ph2, g_h2);
    cudaGetSymbolAddress(&ph3, g_h3);

    const int nb1024 = (M + 1023) / 1024;

    // stage 0a: graph ranges
    find_starts_kernel<<<1, 512>>>(gid, M, G);

    // stage 0b: CSR build
    zero_deg_kernel<<<(M + 255) / 256, 256>>>(M);
    hist_kernel<<<(E + 255) / 256, 256>>>(dst, E);
    block_sums_kernel<<<nb1024, 1024>>>(M);
    scan_bsum_kernel<<<1, 128>>>(nb1024, M, E);
    scan_block_kernel<<<nb1024, 1024>>>(M);
    scatter_kernel<<<(E + 255) / 256, 256>>>(src, dst, E);

    const int MB = (M + 127) / 128;

    // stage 1: m = relu(x @ W_pool + b_pool)
    gemm_tc<128, 0, 128><<<dim3(MB, 1), 256>>>(
        x, nullptr, W_pool, nullptr, b_pool, (float*)pm, M);

    // stage 2: neigh[d] = max over in-edges of m[src]
    gather_max_kernel<<<(M * 32 + 255) / 256, 256>>>(M);

    // stage 3: h1 = relu(x @ W_self + neigh @ W_neigh + b_sage)
    gemm_tc<128, 128, 256><<<dim3(MB, 2), 256>>>(
        x, (const float*)pn, W_self, W_neigh, b_sage, (float*)ph1, M);

    // stage 4/5: MLP
    gemm_tc<256, 0, 256><<<dim3(MB, 2), 256>>>(
        (const float*)ph1, nullptr, W1, nullptr, b1, (float*)ph2, M);
    gemm_tc<256, 0, 256><<<dim3(MB, 2), 256>>>(
        (const float*)ph2, nullptr, W2, nullptr, b2, (float*)ph3, M);

    // stage 6: chunked per-graph softmax denominator -> final = 1/zsum
    softmax_partial_kernel<<<G * SMX_C, HIDD>>>();
    softmax_combine_kernel<<<G, HIDD>>>();

    // stage 7: out = final @ Wr + br
    readout_kernel<<<(G * 2 + 255) / 256, 256>>>(Wr, br, out, G);
}

// round 12
// speedup vs baseline: 1.1079x; 1.0566x over previous
#include <cuda_runtime.h>
#include <cuda_bf16.h>
#include <float.h>

#define NN   100000
#define NE   1600000
#define IND  128
#define HIDD 256
#define NG   256
#define SMX_C 8

// ---------------- static device scratch (allocation-free rule) ----------------
__device__ float g_m[NN * IND];        // relu(x @ W_pool + b_pool)
__device__ float g_neigh[NN * IND];    // segment_max over in-edges
__device__ float g_h1[NN * HIDD];
__device__ float g_h2[NN * HIDD];
__device__ float g_h3[NN * HIDD];
__device__ float g_final[NG * HIDD];   // 1/zsum per (graph, feature)
__device__ int   g_start[NG + 1];      // node range per graph (graph_id sorted)

// CSR scratch
__device__ int g_deg[NN];
__device__ int g_cursor[NN];
__device__ int g_off[NN + 1];
__device__ int g_esrc[NE];
__device__ int g_bsum[128];

// softmax partials
__device__ float g_pmax[NG * SMX_C * HIDD];
__device__ float g_psum[NG * SMX_C * HIDD];

// ---------------- FFMA-pipe exp (no MUFU): exp(x), x <= 0 -------------------
__device__ __forceinline__ float fast_exp(float x) {
    float t = x * 1.4426950408889634f;
    t = fmaxf(t, -126.0f);
    float fi = floorf(t);
    float f  = t - fi;
    float p;
    p = fmaf(f, 1.5252733e-5f, 1.5403530e-4f);
    p = fmaf(f, p, 1.3333558e-3f);
    p = fmaf(f, p, 9.6181291e-3f);
    p = fmaf(f, p, 5.5504109e-2f);
    p = fmaf(f, p, 2.4022651e-1f);
    p = fmaf(f, p, 6.9314718e-1f);
    p = fmaf(f, p, 1.0f);
    int ei = (int)fi;
    float sc = __int_as_float((ei + 127) << 23);
    return p * sc;
}

// ---------------- graph ranges: gid sorted -> binary search ----------------
__global__ void find_starts_kernel(const int* __restrict__ gid, int n, int G) {
    int g = blockIdx.x * blockDim.x + threadIdx.x;
    if (g > G) return;
    int lo = 0, hi = n;
    while (lo < hi) {
        int mid = (lo + hi) >> 1;
        if (gid[mid] < g) lo = mid + 1; else hi = mid;
    }
    g_start[g] = lo;
}

// ---------------- CSR build ----------------
__global__ void zero_deg_kernel(int n) {
    int i = blockIdx.x * blockDim.x + threadIdx.x;
    if (i < n) g_deg[i] = 0;
}
__global__ void hist_kernel(const int* __restrict__ dst, int ne) {
    int e = blockIdx.x * blockDim.x + threadIdx.x;
    if (e < ne) atomicAdd(&g_deg[dst[e]], 1);
}
__global__ void block_sums_kernel(int n) {
    __shared__ int sh[1024];
    int i = blockIdx.x * 1024 + threadIdx.x;
    sh[threadIdx.x] = (i < n) ? g_deg[i] : 0;
    __syncthreads();
    for (int s = 512; s > 0; s >>= 1) {
        if (threadIdx.x < s) sh[threadIdx.x] += sh[threadIdx.x + s];
        __syncthreads();
    }
    if (threadIdx.x == 0) g_bsum[blockIdx.x] = sh[0];
}
__global__ void scan_bsum_kernel(int nb, int n, int ne) {
    __shared__ int sh[128];
    int t = threadIdx.x;
    sh[t] = (t < nb) ? g_bsum[t] : 0;
    __syncthreads();
    for (int d = 1; d < 128; d <<= 1) {
        int v = (t >= d) ? sh[t - d] : 0;
        __syncthreads();
        sh[t] += v;
        __syncthreads();
    }
    if (t < nb) g_bsum[t] = (t == 0) ? 0 : sh[t - 1];
    if (t == 0) g_off[n] = ne;
}
__global__ void scan_block_kernel(int n) {
    __shared__ int sh[1024];
    int t = threadIdx.x;
    int i = blockIdx.x * 1024 + t;
    int v = (i < n) ? g_deg[i] : 0;
    sh[t] = v;
    __syncthreads();
    for (int d = 1; d < 1024; d <<= 1) {
        int u = (t >= d) ? sh[t - d] : 0;
        __syncthreads();
        sh[t] += u;
        __syncthreads();
    }
    if (i < n) {
        int off = g_bsum[blockIdx.x] + sh[t] - v;
        g_off[i] = off;
        g_cursor[i] = off;
    }
}
__global__ void scatter_kernel(const int* __restrict__ src, const int* __restrict__ dst, int ne) {
    int e = blockIdx.x * blockDim.x + threadIdx.x;
    if (e < ne) {
        int pos = atomicAdd(&g_cursor[dst[e]], 1);
        g_esrc[pos] = src[e];
    }
}

// ---------------- gather max: warp per dst node, no atomics ----------------
__global__ void gather_max_kernel(int n) {
    int warp = (blockIdx.x * blockDim.x + threadIdx.x) >> 5;
    if (warp >= n) return;
    int lane = threadIdx.x & 31;
    int c = lane * 4;
    int beg = g_off[warp], end = g_off[warp + 1];
    float4 acc = make_float4(0.f, 0.f, 0.f, 0.f);
    int j = beg;
    for (; j + 2 <= end; j += 2) {
        int s0 = __ldg(&g_esrc[j]);
        int s1 = __ldg(&g_esrc[j + 1]);
        float4 v0 = *reinterpret_cast<const float4*>(&g_m[s0 * IND + c]);
        float4 v1 = *reinterpret_cast<const float4*>(&g_m[s1 * IND + c]);
        acc.x = fmaxf(acc.x, fmaxf(v0.x, v1.x));
        acc.y = fmaxf(acc.y, fmaxf(v0.y, v1.y));
        acc.z = fmaxf(acc.z, fmaxf(v0.z, v1.z));
        acc.w = fmaxf(acc.w, fmaxf(v0.w, v1.w));
    }
    if (j < end) {
        int s0 = __ldg(&g_esrc[j]);
        float4 v0 = *reinterpret_cast<const float4*>(&g_m[s0 * IND + c]);
        acc.x = fmaxf(acc.x, v0.x);
        acc.y = fmaxf(acc.y, v0.y);
        acc.z = fmaxf(acc.z, v0.z);
        acc.w = fmaxf(acc.w, v0.w);
    }
    *reinterpret_cast<float4*>(&g_neigh[warp * IND + c]) = acc;
}

// ---------------- bf16-split tensor-core GEMM, reg-prefetch double-buffer ---
__device__ __forceinline__ void cvt_hl(float x, unsigned short& h, unsigned short& l) {
    __nv_bfloat16 bh = __float2bfloat16(x);
    __nv_bfloat16 bl = __float2bfloat16(x - __bfloat162float(bh));
    h = __bfloat16_as_ushort(bh);
    l = __bfloat16_as_ushort(bl);
}

__device__ __forceinline__ void mma16816(float* d, const unsigned* a, const unsigned* b) {
    asm volatile("mma.sync.aligned.m16n8k16.row.col.f32.bf16.bf16.f32 "
                 "{%0,%1,%2,%3}, {%4,%5,%6,%7}, {%8,%9}, {%0,%1,%2,%3};"
                 : "+f"(d[0]), "+f"(d[1]), "+f"(d[2]), "+f"(d[3])
                 : "r"(a[0]), "r"(a[1]), "r"(a[2]), "r"(a[3]),
                   "r"(b[0]), "r"(b[1]));
}

// smem layout (ushort units), per buffer: A_hi[5120] A_lo[5120] B_hi[5120] B_lo[5120]
// rows padded to 40 shorts (conflict-free 32-bit fragment loads).
template<int K1, int K2, int N>
__global__ __launch_bounds__(256, 2)
void gemm_tc(const float* __restrict__ A1, const float* __restrict__ A2,
             const float* __restrict__ B1, const float* __restrict__ B2,
             const float* __restrict__ bias, float* __restrict__ C, int M)
{
    constexpr int KT = K1 + K2;
    constexpr int T  = KT / 32;
    constexpr int PLANE = 5120;
    constexpr int STG   = 4 * PLANE;    // 20480 shorts per buffer

    extern __shared__ unsigned short sm[];

    const int tid     = threadIdx.x;
    const int rowbase = blockIdx.x * 128;
    const int colbase = blockIdx.y * 128;

    const int lane = tid & 31;
    const int wid  = tid >> 5;
    const int wm   = (wid & 3) * 32;
    const int wn   = (wid >> 2) * 64;
    const int fr   = lane >> 2;
    const int fc   = (lane & 3) * 2;

    const int a_row = tid >> 1;
    const int a_k0  = (tid & 1) * 16;
    const int a_grow = rowbase + a_row;
    const bool a_ok  = a_grow < M;
    const int b_n   = tid & 127;
    const int b_kqb = tid >> 7;

    float acc[2][8][4];
#pragma unroll
    for (int mt = 0; mt < 2; ++mt)
#pragma unroll
        for (int nt = 0; nt < 8; ++nt)
#pragma unroll
            for (int q = 0; q < 4; ++q) acc[mt][nt][q] = 0.f;

    float4 pa[4];        // A staging regs: 16 fp32
    float  pb[4][4];     // B staging regs: 16 fp32

    auto loadTile = [&](int t) {
        const int kc = t * 32;
        // A
        const float* ap;
        if constexpr (K2 == 0) {
            ap = A1 + (size_t)a_grow * K1 + kc + a_k0;
        } else {
            ap = (kc < K1) ? A1 + (size_t)a_grow * K1 + kc + a_k0
                           : A2 + (size_t)a_grow * K2 + (kc - K1) + a_k0;
        }
#pragma unroll
        for (int i = 0; i < 4; ++i)
            pa[i] = a_ok ? *reinterpret_cast<const float4*>(ap + i * 4)
                         : make_float4(0.f, 0.f, 0.f, 0.f);
        // B (strided scalar loads; each instr is a coalesced 128B warp access)
#pragma unroll
        for (int it = 0; it < 4; ++it) {
            int kq = it * 2 + b_kqb;
            int kg = kc + kq * 4;
            const float* bp;
            if constexpr (K2 == 0) {
                bp = B1 + (size_t)kg * N + colbase + b_n;
            } else {
                bp = (kg < K1) ? B1 + (size_t)kg * N + colbase + b_n
                               : B2 + (size_t)(kg - K1) * N + colbase + b_n;
            }
#pragma unroll
            for (int i = 0; i < 4; ++i) pb[it][i] = bp[(size_t)i * N];
        }
    };

    auto storeTile = [&](int buf) {
        unsigned short* Ah = sm + buf * STG;
        unsigned short* Al = Ah + PLANE;
        unsigned short* Bh = Ah + 2 * PLANE;
        unsigned short* Bl = Ah + 3 * PLANE;
#pragma unroll
        for (int i = 0; i < 4; ++i) {
            unsigned short h[4], l[4];
            cvt_hl(pa[i].x, h[0], l[0]); cvt_hl(pa[i].y, h[1], l[1]);
            cvt_hl(pa[i].z, h[2], l[2]); cvt_hl(pa[i].w, h[3], l[3]);
            uint2 hw, lw;
            hw.x = ((unsigned)h[1] << 16) | h[0];
            hw.y = ((unsigned)h[3] << 16) | h[2];
            lw.x = ((unsigned)l[1] << 16) | l[0];
            lw.y = ((unsigned)l[3] << 16) | l[2];
            *reinterpret_cast<uint2*>(&Ah[a_row * 40 + a_k0 + i * 4]) = hw;
            *reinterpret_cast<uint2*>(&Al[a_row * 40 + a_k0 + i * 4]) = lw;
        }
#pragma unroll
        for (int it = 0; it < 4; ++it) {
            int kq = it * 2 + b_kqb;
            unsigned short h[4], l[4];
#pragma unroll
            for (int i = 0; i < 4; ++i) cvt_hl(pb[it][i], h[i], l[i]);
            uint2 hw, lw;
            hw.x = ((unsigned)h[1] << 16) | h[0];
            hw.y = ((unsigned)h[3] << 16) | h[2];
            lw.x = ((unsigned)l[1] << 16) | l[0];
            lw.y = ((unsigned)l[3] << 16) | l[2];
            *reinterpret_cast<uint2*>(&Bh[b_n * 40 + kq * 4]) = hw;
            *reinterpret_cast<uint2*>(&Bl[b_n * 40 + kq * 4]) = lw;
        }
    };

    // prologue: stage tile 0
    loadTile(0);
    storeTile(0);
    __syncthreads();

#pragma unroll 1
    for (int t = 0; t < T; ++t) {
        if (t + 1 < T) loadTile(t + 1);   // LDG issued before compute -> latency hidden

        const unsigned short* Ah = sm + (t & 1) * STG;
        const unsigned short* Al = Ah + PLANE;
        const unsigned short* Bh = Ah + 2 * PLANE;
        const unsigned short* Bl = Ah + 3 * PLANE;

#pragma unroll
        for (int kk = 0; kk < 32; kk += 16) {
            unsigned ah[2][4], al[2][4];
#pragma unroll
            for (int mt = 0; mt < 2; ++mt) {
                int r0 = wm + mt * 16 + fr;
                ah[mt][0] = *reinterpret_cast<const unsigned*>(&Ah[r0 * 40 + kk + fc]);
                ah[mt][1] = *reinterpret_cast<const unsigned*>(&Ah[(r0 + 8) * 40 + kk + fc]);
                ah[mt][2] = *reinterpret_cast<const unsigned*>(&Ah[r0 * 40 + kk + fc + 8]);
                ah[mt][3] = *reinterpret_cast<const unsigned*>(&Ah[(r0 + 8) * 40 + kk + fc + 8]);
                al[mt][0] = *reinterpret_cast<const unsigned*>(&Al[r0 * 40 + kk + fc]);
                al[mt][1] = *reinterpret_cast<const unsigned*>(&Al[(r0 + 8) * 40 + kk + fc]);
                al[mt][2] = *reinterpret_cast<const unsigned*>(&Al[r0 * 40 + kk + fc + 8]);
                al[mt][3] = *reinterpret_cast<const unsigned*>(&Al[(r0 + 8) * 40 + kk + fc + 8]);
            }
#pragma unroll
            for (int nt = 0; nt < 8; ++nt) {
                int nb = wn + nt * 8 + fr;
                unsigned bh[2], bl[2];
                bh[0] = *reinterpret_cast<const unsigned*>(&Bh[nb * 40 + kk + fc]);
                bh[1] = *reinterpret_cast<const unsigned*>(&Bh[nb * 40 + kk + fc + 8]);
                bl[0] = *reinterpret_cast<const unsigned*>(&Bl[nb * 40 + kk + fc]);
                bl[1] = *reinterpret_cast<const unsigned*>(&Bl[nb * 40 + kk + fc + 8]);
#pragma unroll
                for (int mt = 0; mt < 2; ++mt) {
                    mma16816(acc[mt][nt], ah[mt], bh);
                    mma16816(acc[mt][nt], ah[mt], bl);
                    mma16816(acc[mt][nt], al[mt], bh);
                }
            }
        }

        if (t + 1 < T) storeTile((t + 1) & 1);   // cvt+STS into other buffer
        __syncthreads();
    }

    // ---- epilogue: bias + relu ----
#pragma unroll
    for (int nt = 0; nt < 8; ++nt) {
        int cb = colbase + wn + nt * 8 + fc;
        float2 bi = *reinterpret_cast<const float2*>(&bias[cb]);
#pragma unroll
        for (int mt = 0; mt < 2; ++mt) {
            int r0 = rowbase + wm + mt * 16 + fr;
            if (r0 < M) {
                float2 o;
                o.x = fmaxf(acc[mt][nt][0] + bi.x, 0.f);
                o.y = fmaxf(acc[mt][nt][1] + bi.y, 0.f);
                *reinterpret_cast<float2*>(&C[(size_t)r0 * N + cb]) = o;
            }
            if (r0 + 8 < M) {
                float2 o;
                o.x = fmaxf(acc[mt][nt][2] + bi.x, 0.f);
                o.y = fmaxf(acc[mt][nt][3] + bi.y, 0.f);
                *reinterpret_cast<float2*>(&C[(size_t)(r0 + 8) * N + cb]) = o;
            }
        }
    }
}

// ---------------- chunked per-graph softmax denominator (FFMA exp) ----------
__global__ void softmax_partial_kernel()
{
    int b = blockIdx.x;
    int g = b >> 3, c = b & (SMX_C - 1);
    int s = g_start[g], e = g_start[g + 1];
    int len = e - s;
    int chunk = (len + SMX_C - 1) >> 3;
    int cs = s + c * chunk;
    int ce = min(cs + chunk, e);
    int f = threadIdx.x;
    const float* __restrict__ h = g_h3;

    float mx0 = -FLT_MAX, mx1 = -FLT_MAX;
    float s0 = 0.f, s1 = 0.f;
    int i = cs;
    for (; i + 2 <= ce; i += 2) {
        float v0 = h[(size_t)(i + 0) * HIDD + f];
        float v1 = h[(size_t)(i + 1) * HIDD + f];
        if (v0 > mx0) { s0 *= fast_exp(mx0 - v0); mx0 = v0; }
        s0 += fast_exp(v0 - mx0);
        if (v1 > mx1) { s1 *= fast_exp(mx1 - v1); mx1 = v1; }
        s1 += fast_exp(v1 - mx1);
    }
    for (; i < ce; ++i) {
        float v = h[(size_t)i * HIDD + f];
        if (v > mx0) { s0 *= fast_exp(mx0 - v); mx0 = v; }
        s0 += fast_exp(v - mx0);
    }
    float mx, sm;
    if (cs >= ce) { mx = -FLT_MAX; sm = 0.f; }
    else {
        mx = fmaxf(mx0, mx1);
        sm = s0 * fast_exp(mx0 - mx) + ((s1 > 0.f) ? s1 * fast_exp(mx1 - mx) : 0.f);
    }
    g_pmax[(size_t)b * HIDD + f] = mx;
    g_psum[(size_t)b * HIDD + f] = sm;
}

__global__ void softmax_combine_kernel()
{
    int g = blockIdx.x;
    int f = threadIdx.x;
    float Mx = -FLT_MAX;
#pragma unroll
    for (int c = 0; c < SMX_C; ++c)
        Mx = fmaxf(Mx, g_pmax[(size_t)(g * SMX_C + c) * HIDD + f]);
    float S = 0.f;
#pragma unroll
    for (int c = 0; c < SMX_C; ++c) {
        float pm = g_pmax[(size_t)(g * SMX_C + c) * HIDD + f];
        float ps = g_psum[(size_t)(g * SMX_C + c) * HIDD + f];
        if (ps > 0.f) S += ps * fast_exp(pm - Mx);
    }
    g_final[g * HIDD + f] = (g_start[g + 1] > g_start[g]) ? (1.0f / S) : 0.f;
}

// ---------------- tiny readout: out = final @ Wr + br ----------------
__global__ void readout_kernel(const float* __restrict__ Wr, const float* __restrict__ br,
                               float* __restrict__ out, int ngr)
{
    int t = blockIdx.x * blockDim.x + threadIdx.x;
    if (t < ngr * 2) {
        int g = t >> 1, o = t & 1;
        float acc = br[o];
        const float* fr = &g_final[g * HIDD];
#pragma unroll 8
        for (int f = 0; f < HIDD; ++f) acc = fmaf(fr[f], Wr[f * 2 + o], acc);
        out[t] = acc;
    }
}

// ---------------- launch ----------------
extern "C" void kernel_launch(void* const* d_in, const int* in_sizes, int n_in,
                              void* d_out, int out_size)
{
    const float* x       = (const float*)d_in[0];
    const float* W_pool  = (const float*)d_in[1];
    const float* b_pool  = (const float*)d_in[2];
    const float* W_self  = (const float*)d_in[3];
    const float* W_neigh = (const float*)d_in[4];
    const float* b_sage  = (const float*)d_in[5];
    const float* W1      = (const float*)d_in[6];
    const float* b1      = (const float*)d_in[7];
    const float* W2      = (const float*)d_in[8];
    const float* b2      = (const float*)d_in[9];
    const float* Wr      = (const float*)d_in[10];
    const float* br      = (const float*)d_in[11];
    const int*   src     = (const int*)d_in[12];
    const int*   dst     = (const int*)d_in[13];
    const int*   gid     = (const int*)d_in[14];
    float*       out     = (float*)d_out;

    const int M = in_sizes[0] / IND;   // 100000
    const int E = in_sizes[12];        // 1600000
    const int G = out_size / 2;        // 256

    const int SMEM_BYTES = 2 * 20480 * 2;   // 2 buffers x 20480 shorts = 80 KB

    cudaFuncSetAttribute((const void*)gemm_tc<128, 0, 128>,
                         cudaFuncAttributeMaxDynamicSharedMemorySize, SMEM_BYTES);
    cudaFuncSetAttribute((const void*)gemm_tc<128, 128, 256>,
                         cudaFuncAttributeMaxDynamicSharedMemorySize, SMEM_BYTES);
    cudaFuncSetAttribute((const void*)gemm_tc<256, 0, 256>,
                         cudaFuncAttributeMaxDynamicSharedMemorySize, SMEM_BYTES);

    void *pm, *pn, *ph1, *ph2, *ph3;
    cudaGetSymbolAddress(&pm,  g_m);
    cudaGetSymbolAddress(&pn,  g_neigh);
    cudaGetSymbolAddress(&ph1, g_h1);
    cudaGetSymbolAddress(&ph2, g_h2);
    cudaGetSymbolAddress(&ph3, g_h3);

    const int nb1024 = (M + 1023) / 1024;

    // stage 0a: graph ranges
    find_starts_kernel<<<1, 512>>>(gid, M, G);

    // stage 0b: CSR build
    zero_deg_kernel<<<(M + 255) / 256, 256>>>(M);
    hist_kernel<<<(E + 255) / 256, 256>>>(dst, E);
    block_sums_kernel<<<nb1024, 1024>>>(M);
    scan_bsum_kernel<<<1, 128>>>(nb1024, M, E);
    scan_block_kernel<<<nb1024, 1024>>>(M);
    scatter_kernel<<<(E + 255) / 256, 256>>>(src, dst, E);

    const int MB = (M + 127) / 128;

    // stage 1: m = relu(x @ W_pool + b_pool)
    gemm_tc<128, 0, 128><<<dim3(MB, 1), 256, SMEM_BYTES>>>(
        x, nullptr, W_pool, nullptr, b_pool, (float*)pm, M);

    // stage 2: neigh[d] = max over in-edges of m[src]
    gather_max_kernel<<<(M * 32 + 255) / 256, 256>>>(M);

    // stage 3: h1 = relu(x @ W_self + neigh @ W_neigh + b_sage)
    gemm_tc<128, 128, 256><<<dim3(MB, 2), 256, SMEM_BYTES>>>(
        x, (const float*)pn, W_self, W_neigh, b_sage, (float*)ph1, M);

    // stage 4/5: MLP
    gemm_tc<256, 0, 256><<<dim3(MB, 2), 256, SMEM_BYTES>>>(
        (const float*)ph1, nullptr, W1, nullptr, b1, (float*)ph2, M);
    gemm_tc<256, 0, 256><<<dim3(MB, 2), 256, SMEM_BYTES>>>(
        (const float*)ph2, nullptr, W2, nullptr, b2, (float*)ph3, M);

    // stage 6: chunked per-graph softmax denominator -> final = 1/zsum
    softmax_partial_kernel<<<G * SMX_C, HIDD>>>();
    softmax_combine_kernel<<<G, HIDD>>>();

    // stage 7: out = final @ Wr + br
    readout_kernel<<<(G * 2 + 255) / 256, 256>>>(Wr, br, out, G);
}

// round 13
// speedup vs baseline: 1.1607x; 1.0476x over previous
#include <cuda_runtime.h>
#include <cuda_bf16.h>
#include <cuda_fp16.h>
#include <float.h>

#define NN   100000
#define NE   1600000
#define IND  128
#define HIDD 256
#define NG   256
#define SMX_C 8

// ---------------- static device scratch (allocation-free rule) ----------------
__device__ __half g_m16[NN * IND];     // relu(x @ W_pool + b_pool), fp16
__device__ float g_neigh[NN * IND];    // segment_max over in-edges
__device__ float g_h1[NN * HIDD];
__device__ float g_h2[NN * HIDD];
__device__ float g_h3[NN * HIDD];
__device__ float g_final[NG * HIDD];   // 1/zsum per (graph, feature)
__device__ int   g_start[NG + 1];      // node range per graph (graph_id sorted)

// CSR scratch
__device__ int g_deg[NN];
__device__ int g_cursor[NN];
__device__ int g_off[NN + 1];
__device__ int g_esrc[NE];
__device__ int g_bsum[128];

// softmax partials
__device__ float g_pmax[NG * SMX_C * HIDD];
__device__ float g_psum[NG * SMX_C * HIDD];

// ---------------- FFMA-pipe exp (no MUFU): exp(x), x <= 0 -------------------
__device__ __forceinline__ float fast_exp(float x) {
    float t = x * 1.4426950408889634f;
    t = fmaxf(t, -126.0f);
    float fi = floorf(t);
    float f  = t - fi;
    float p;
    p = fmaf(f, 1.5252733e-5f, 1.5403530e-4f);
    p = fmaf(f, p, 1.3333558e-3f);
    p = fmaf(f, p, 9.6181291e-3f);
    p = fmaf(f, p, 5.5504109e-2f);
    p = fmaf(f, p, 2.4022651e-1f);
    p = fmaf(f, p, 6.9314718e-1f);
    p = fmaf(f, p, 1.0f);
    int ei = (int)fi;
    float sc = __int_as_float((ei + 127) << 23);
    return p * sc;
}

// ---------------- graph ranges: gid sorted -> binary search ----------------
__global__ void find_starts_kernel(const int* __restrict__ gid, int n, int G) {
    int g = blockIdx.x * blockDim.x + threadIdx.x;
    if (g > G) return;
    int lo = 0, hi = n;
    while (lo < hi) {
        int mid = (lo + hi) >> 1;
        if (gid[mid] < g) lo = mid + 1; else hi = mid;
    }
    g_start[g] = lo;
}

// ---------------- CSR build ----------------
__global__ void zero_deg_kernel(int n) {
    int i = blockIdx.x * blockDim.x + threadIdx.x;
    if (i < n) g_deg[i] = 0;
}
__global__ void hist_kernel(const int* __restrict__ dst, int ne) {
    int e = blockIdx.x * blockDim.x + threadIdx.x;
    if (e < ne) atomicAdd(&g_deg[dst[e]], 1);
}
__global__ void block_sums_kernel(int n) {
    __shared__ int sh[1024];
    int i = blockIdx.x * 1024 + threadIdx.x;
    sh[threadIdx.x] = (i < n) ? g_deg[i] : 0;
    __syncthreads();
    for (int s = 512; s > 0; s >>= 1) {
        if (threadIdx.x < s) sh[threadIdx.x] += sh[threadIdx.x + s];
        __syncthreads();
    }
    if (threadIdx.x == 0) g_bsum[blockIdx.x] = sh[0];
}
__global__ void scan_bsum_kernel(int nb, int n, int ne) {
    __shared__ int sh[128];
    int t = threadIdx.x;
    sh[t] = (t < nb) ? g_bsum[t] : 0;
    __syncthreads();
    for (int d = 1; d < 128; d <<= 1) {
        int v = (t >= d) ? sh[t - d] : 0;
        __syncthreads();
        sh[t] += v;
        __syncthreads();
    }
    if (t < nb) g_bsum[t] = (t == 0) ? 0 : sh[t - 1];
    if (t == 0) g_off[n] = ne;
}
__global__ void scan_block_kernel(int n) {
    __shared__ int sh[1024];
    int t = threadIdx.x;
    int i = blockIdx.x * 1024 + t;
    int v = (i < n) ? g_deg[i] : 0;
    sh[t] = v;
    __syncthreads();
    for (int d = 1; d < 1024; d <<= 1) {
        int u = (t >= d) ? sh[t - d] : 0;
        __syncthreads();
        sh[t] += u;
        __syncthreads();
    }
    if (i < n) {
        int off = g_bsum[blockIdx.x] + sh[t] - v;
        g_off[i] = off;
        g_cursor[i] = off;
    }
}
__global__ void scatter_kernel(const int* __restrict__ src, const int* __restrict__ dst, int ne) {
    int e = blockIdx.x * blockDim.x + threadIdx.x;
    if (e < ne) {
        int pos = atomicAdd(&g_cursor[dst[e]], 1);
        g_esrc[pos] = src[e];
    }
}

// ---------------- gather max: warp per dst node, fp16 source ----------------
__global__ void gather_max_kernel(int n) {
    int warp = (blockIdx.x * blockDim.x + threadIdx.x) >> 5;
    if (warp >= n) return;
    int lane = threadIdx.x & 31;
    int c = lane * 4;
    int beg = g_off[warp], end = g_off[warp + 1];
    __half2 z = __floats2half2_rn(0.f, 0.f);
    __half2 a01 = z, a23 = z;
    int j = beg;
    for (; j + 2 <= end; j += 2) {
        int s0 = __ldg(&g_esrc[j]);
        int s1 = __ldg(&g_esrc[j + 1]);
        uint2 w0 = *reinterpret_cast<const uint2*>(&g_m16[s0 * IND + c]);
        uint2 w1 = *reinterpret_cast<const uint2*>(&g_m16[s1 * IND + c]);
        a01 = __hmax2(a01, __hmax2(*(__half2*)&w0.x, *(__half2*)&w1.x));
        a23 = __hmax2(a23, __hmax2(*(__half2*)&w0.y, *(__half2*)&w1.y));
    }
    if (j < end) {
        int s0 = __ldg(&g_esrc[j]);
        uint2 w0 = *reinterpret_cast<const uint2*>(&g_m16[s0 * IND + c]);
        a01 = __hmax2(a01, *(__half2*)&w0.x);
        a23 = __hmax2(a23, *(__half2*)&w0.y);
    }
    float2 f01 = __half22float2(a01);
    float2 f23 = __half22float2(a23);
    *reinterpret_cast<float4*>(&g_neigh[warp * IND + c]) =
        make_float4(f01.x, f01.y, f23.x, f23.y);
}

// ---------------- bf16-split tensor-core GEMM, reg-prefetch double-buffer ---
__device__ __forceinline__ void cvt_hl(float x, unsigned short& h, unsigned short& l) {
    __nv_bfloat16 bh = __float2bfloat16(x);
    __nv_bfloat16 bl = __float2bfloat16(x - __bfloat162float(bh));
    h = __bfloat16_as_ushort(bh);
    l = __bfloat16_as_ushort(bl);
}

__device__ __forceinline__ void mma16816(float* d, const unsigned* a, const unsigned* b) {
    asm volatile("mma.sync.aligned.m16n8k16.row.col.f32.bf16.bf16.f32 "
                 "{%0,%1,%2,%3}, {%4,%5,%6,%7}, {%8,%9}, {%0,%1,%2,%3};"
                 : "+f"(d[0]), "+f"(d[1]), "+f"(d[2]), "+f"(d[3])
                 : "r"(a[0]), "r"(a[1]), "r"(a[2]), "r"(a[3]),
                   "r"(b[0]), "r"(b[1]));
}

// smem per buffer: A_hi[5120] A_lo[5120] B_hi[5120] B_lo[5120] shorts, rows pad 40.
// OUTH=1: write __half2 to Ch; else float2 to C.
template<int K1, int K2, int N, int OUTH>
__global__ __launch_bounds__(256, 2)
void gemm_tc(const float* __restrict__ A1, const float* __restrict__ A2,
             const float* __restrict__ B1, const float* __restrict__ B2,
             const float* __restrict__ bias, float* __restrict__ C,
             __half* __restrict__ Ch, int M)
{
    constexpr int KT = K1 + K2;
    constexpr int T  = KT / 32;
    constexpr int PLANE = 5120;
    constexpr int STG   = 4 * PLANE;

    extern __shared__ unsigned short sm[];

    const int tid     = threadIdx.x;
    const int rowbase = blockIdx.x * 128;
    const int colbase = blockIdx.y * 128;

    const int lane = tid & 31;
    const int wid  = tid >> 5;
    const int wm   = (wid & 3) * 32;
    const int wn   = (wid >> 2) * 64;
    const int fr   = lane >> 2;
    const int fc   = (lane & 3) * 2;

    const int a_row = tid >> 1;
    const int a_k0  = (tid & 1) * 16;
    const int a_grow = rowbase + a_row;
    const bool a_ok  = a_grow < M;
    const int b_n   = tid & 127;
    const int b_kqb = tid >> 7;

    float acc[2][8][4];
#pragma unroll
    for (int mt = 0; mt < 2; ++mt)
#pragma unroll
        for (int nt = 0; nt < 8; ++nt)
#pragma unroll
            for (int q = 0; q < 4; ++q) acc[mt][nt][q] = 0.f;

    float4 pa[4];
    float  pb[4][4];

    auto loadTile = [&](int t) {
        const int kc = t * 32;
        const float* ap;
        if constexpr (K2 == 0) {
            ap = A1 + (size_t)a_grow * K1 + kc + a_k0;
        } else {
            ap = (kc < K1) ? A1 + (size_t)a_grow * K1 + kc + a_k0
                           : A2 + (size_t)a_grow * K2 + (kc - K1) + a_k0;
        }
#pragma unroll
        for (int i = 0; i < 4; ++i)
            pa[i] = a_ok ? *reinterpret_cast<const float4*>(ap + i * 4)
                         : make_float4(0.f, 0.f, 0.f, 0.f);
#pragma unroll
        for (int it = 0; it < 4; ++it) {
            int kq = it * 2 + b_kqb;
            int kg = kc + kq * 4;
            const float* bp;
            if constexpr (K2 == 0) {
                bp = B1 + (size_t)kg * N + colbase + b_n;
            } else {
                bp = (kg < K1) ? B1 + (size_t)kg * N + colbase + b_n
                               : B2 + (size_t)(kg - K1) * N + colbase + b_n;
            }
#pragma unroll
            for (int i = 0; i < 4; ++i) pb[it][i] = bp[(size_t)i * N];
        }
    };

    auto storeTile = [&](int buf) {
        unsigned short* Ah = sm + buf * STG;
        unsigned short* Al = Ah + PLANE;
        unsigned short* Bh = Ah + 2 * PLANE;
        unsigned short* Bl = Ah + 3 * PLANE;
#pragma unroll
        for (int i = 0; i < 4; ++i) {
            unsigned short h[4], l[4];
            cvt_hl(pa[i].x, h[0], l[0]); cvt_hl(pa[i].y, h[1], l[1]);
            cvt_hl(pa[i].z, h[2], l[2]); cvt_hl(pa[i].w, h[3], l[3]);
            uint2 hw, lw;
            hw.x = ((unsigned)h[1] << 16) | h[0];
            hw.y = ((unsigned)h[3] << 16) | h[2];
            lw.x = ((unsigned)l[1] << 16) | l[0];
            lw.y = ((unsigned)l[3] << 16) | l[2];
            *reinterpret_cast<uint2*>(&Ah[a_row * 40 + a_k0 + i * 4]) = hw;
            *reinterpret_cast<uint2*>(&Al[a_row * 40 + a_k0 + i * 4]) = lw;
        }
#pragma unroll
        for (int it = 0; it < 4; ++it) {
            int kq = it * 2 + b_kqb;
            unsigned short h[4], l[4];
#pragma unroll
            for (int i = 0; i < 4; ++i) cvt_hl(pb[it][i], h[i], l[i]);
            uint2 hw, lw;
            hw.x = ((unsigned)h[1] << 16) | h[0];
            hw.y = ((unsigned)h[3] << 16) | h[2];
            lw.x = ((unsigned)l[1] << 16) | l[0];
            lw.y = ((unsigned)l[3] << 16) | l[2];
            *reinterpret_cast<uint2*>(&Bh[b_n * 40 + kq * 4]) = hw;
            *reinterpret_cast<uint2*>(&Bl[b_n * 40 + kq * 4]) = lw;
        }
    };

    loadTile(0);
    storeTile(0);
    __syncthreads();

#pragma unroll 1
    for (int t = 0; t < T; ++t) {
        if (t + 1 < T) loadTile(t + 1);

        const unsigned short* Ah = sm + (t & 1) * STG;
        const unsigned short* Al = Ah + PLANE;
        const unsigned short* Bh = Ah + 2 * PLANE;
        const unsigned short* Bl = Ah + 3 * PLANE;

#pragma unroll
        for (int kk = 0; kk < 32; kk += 16) {
            unsigned ah[2][4], al[2][4];
#pragma unroll
            for (int mt = 0; mt < 2; ++mt) {
                int r0 = wm + mt * 16 + fr;
                ah[mt][0] = *reinterpret_cast<const unsigned*>(&Ah[r0 * 40 + kk + fc]);
                ah[mt][1] = *reinterpret_cast<const unsigned*>(&Ah[(r0 + 8) * 40 + kk + fc]);
                ah[mt][2] = *reinterpret_cast<const unsigned*>(&Ah[r0 * 40 + kk + fc + 8]);
                ah[mt][3] = *reinterpret_cast<const unsigned*>(&Ah[(r0 + 8) * 40 + kk + fc + 8]);
                al[mt][0] = *reinterpret_cast<const unsigned*>(&Al[r0 * 40 + kk + fc]);
                al[mt][1] = *reinterpret_cast<const unsigned*>(&Al[(r0 + 8) * 40 + kk + fc]);
                al[mt][2] = *reinterpret_cast<const unsigned*>(&Al[r0 * 40 + kk + fc + 8]);
                al[mt][3] = *reinterpret_cast<const unsigned*>(&Al[(r0 + 8) * 40 + kk + fc + 8]);
            }
#pragma unroll
            for (int nt = 0; nt < 8; ++nt) {
                int nb = wn + nt * 8 + fr;
                unsigned bh[2], bl[2];
                bh[0] = *reinterpret_cast<const unsigned*>(&Bh[nb * 40 + kk + fc]);
                bh[1] = *reinterpret_cast<const unsigned*>(&Bh[nb * 40 + kk + fc + 8]);
                bl[0] = *reinterpret_cast<const unsigned*>(&Bl[nb * 40 + kk + fc]);
                bl[1] = *reinterpret_cast<const unsigned*>(&Bl[nb * 40 + kk + fc + 8]);
#pragma unroll
                for (int mt = 0; mt < 2; ++mt) {
                    mma16816(acc[mt][nt], ah[mt], bh);
                    mma16816(acc[mt][nt], ah[mt], bl);
                    mma16816(acc[mt][nt], al[mt], bh);
                }
            }
        }

        if (t + 1 < T) storeTile((t + 1) & 1);
        __syncthreads();
    }

    // ---- epilogue: bias + relu ----
#pragma unroll
    for (int nt = 0; nt < 8; ++nt) {
        int cb = colbase + wn + nt * 8 + fc;
        float2 bi = *reinterpret_cast<const float2*>(&bias[cb]);
#pragma unroll
        for (int mt = 0; mt < 2; ++mt) {
            int r0 = rowbase + wm + mt * 16 + fr;
#pragma unroll
            for (int half = 0; half < 2; ++half) {
                int r = r0 + half * 8;
                if (r < M) {
                    float vx = fmaxf(acc[mt][nt][half * 2 + 0] + bi.x, 0.f);
                    float vy = fmaxf(acc[mt][nt][half * 2 + 1] + bi.y, 0.f);
                    if constexpr (OUTH) {
                        *reinterpret_cast<__half2*>(&Ch[(size_t)r * N + cb]) =
                            __floats2half2_rn(vx, vy);
                    } else {
                        *reinterpret_cast<float2*>(&C[(size_t)r * N + cb]) =
                            make_float2(vx, vy);
                    }
                }
            }
        }
    }
}

// ---------------- chunked per-graph softmax denominator (FFMA exp) ----------
__global__ void softmax_partial_kernel()
{
    int b = blockIdx.x;
    int g = b >> 3, c = b & (SMX_C - 1);
    int s = g_start[g], e = g_start[g + 1];
    int len = e - s;
    int chunk = (len + SMX_C - 1) >> 3;
    int cs = s + c * chunk;
    int ce = min(cs + chunk, e);
    int f = threadIdx.x;
    const float* __restrict__ h = g_h3;

    float mx0 = -FLT_MAX, mx1 = -FLT_MAX;
    float s0 = 0.f, s1 = 0.f;
    int i = cs;
    for (; i + 2 <= ce; i += 2) {
        float v0 = h[(size_t)(i + 0) * HIDD + f];
        float v1 = h[(size_t)(i + 1) * HIDD + f];
        if (v0 > mx0) { s0 *= fast_exp(mx0 - v0); mx0 = v0; }
        s0 += fast_exp(v0 - mx0);
        if (v1 > mx1) { s1 *= fast_exp(mx1 - v1); mx1 = v1; }
        s1 += fast_exp(v1 - mx1);
    }
    for (; i < ce; ++i) {
        float v = h[(size_t)i * HIDD + f];
        if (v > mx0) { s0 *= fast_exp(mx0 - v); mx0 = v; }
        s0 += fast_exp(v - mx0);
    }
    float mx, sm;
    if (cs >= ce) { mx = -FLT_MAX; sm = 0.f; }
    else {
        mx = fmaxf(mx0, mx1);
        sm = s0 * fast_exp(mx0 - mx) + ((s1 > 0.f) ? s1 * fast_exp(mx1 - mx) : 0.f);
    }
    g_pmax[(size_t)b * HIDD + f] = mx;
    g_psum[(size_t)b * HIDD + f] = sm;
}

__global__ void softmax_combine_kernel()
{
    int g = blockIdx.x;
    int f = threadIdx.x;
    float Mx = -FLT_MAX;
#pragma unroll
    for (int c = 0; c < SMX_C; ++c)
        Mx = fmaxf(Mx, g_pmax[(size_t)(g * SMX_C + c) * HIDD + f]);
    float S = 0.f;
#pragma unroll
    for (int c = 0; c < SMX_C; ++c) {
        float pm = g_pmax[(size_t)(g * SMX_C + c) * HIDD + f];
        float ps = g_psum[(size_t)(g * SMX_C + c) * HIDD + f];
        if (ps > 0.f) S += ps * fast_exp(pm - Mx);
    }
    g_final[g * HIDD + f] = (g_start[g + 1] > g_start[g]) ? (1.0f / S) : 0.f;
}

// ---------------- tiny readout: out = final @ Wr + br ----------------
__global__ void readout_kernel(const float* __restrict__ Wr, const float* __restrict__ br,
                               float* __restrict__ out, int ngr)
{
    int t = blockIdx.x * blockDim.x + threadIdx.x;
    if (t < ngr * 2) {
        int g = t >> 1, o = t & 1;
        float acc = br[o];
        const float* fr = &g_final[g * HIDD];
#pragma unroll 8
        for (int f = 0; f < HIDD; ++f) acc = fmaf(fr[f], Wr[f * 2 + o], acc);
        out[t] = acc;
    }
}

// ---------------- launch ----------------
extern "C" void kernel_launch(void* const* d_in, const int* in_sizes, int n_in,
                              void* d_out, int out_size)
{
    const float* x       = (const float*)d_in[0];
    const float* W_pool  = (const float*)d_in[1];
    const float* b_pool  = (const float*)d_in[2];
    const float* W_self  = (const float*)d_in[3];
    const float* W_neigh = (const float*)d_in[4];
    const float* b_sage  = (const float*)d_in[5];
    const float* W1      = (const float*)d_in[6];
    const float* b1      = (const float*)d_in[7];
    const float* W2      = (const float*)d_in[8];
    const float* b2      = (const float*)d_in[9];
    const float* Wr      = (const float*)d_in[10];
    const float* br      = (const float*)d_in[11];
    const int*   src     = (const int*)d_in[12];
    const int*   dst     = (const int*)d_in[13];
    const int*   gid     = (const int*)d_in[14];
    float*       out     = (float*)d_out;

    const int M = in_sizes[0] / IND;   // 100000
    const int E = in_sizes[12];        // 1600000
    const int G = out_size / 2;        // 256

    const int SMEM_BYTES = 2 * 20480 * 2;   // 2 buffers x 20480 shorts = 80 KB

    cudaFuncSetAttribute((const void*)gemm_tc<128, 0, 128, 1>,
                         cudaFuncAttributeMaxDynamicSharedMemorySize, SMEM_BYTES);
    cudaFuncSetAttribute((const void*)gemm_tc<128, 128, 256, 0>,
                         cudaFuncAttributeMaxDynamicSharedMemorySize, SMEM_BYTES);
    cudaFuncSetAttribute((const void*)gemm_tc<256, 0, 256, 0>,
                         cudaFuncAttributeMaxDynamicSharedMemorySize, SMEM_BYTES);

    // side stream + events (created once, outside any graph capture)
    static cudaStream_t s_csr = nullptr;
    static cudaEvent_t  ev_fork = nullptr, ev_join = nullptr;
    if (s_csr == nullptr) {
        cudaStreamCreateWithFlags(&s_csr, cudaStreamNonBlocking);
        cudaEventCreateWithFlags(&ev_fork, cudaEventDisableTiming);
        cudaEventCreateWithFlags(&ev_join, cudaEventDisableTiming);
    }

    void *pm16, *pn, *ph1, *ph2, *ph3;
    cudaGetSymbolAddress(&pm16, g_m16);
    cudaGetSymbolAddress(&pn,  g_neigh);
    cudaGetSymbolAddress(&ph1, g_h1);
    cudaGetSymbolAddress(&ph2, g_h2);
    cudaGetSymbolAddress(&ph3, g_h3);

    const int nb1024 = (M + 1023) / 1024;
    const int MB = (M + 127) / 128;

    // ---- fork: CSR build + graph ranges on side stream ----
    cudaEventRecord(ev_fork, 0);
    cudaStreamWaitEvent(s_csr, ev_fork, 0);
    find_starts_kernel<<<1, 512, 0, s_csr>>>(gid, M, G);
    zero_deg_kernel<<<(M + 255) / 256, 256, 0, s_csr>>>(M);
    hist_kernel<<<(E + 255) / 256, 256, 0, s_csr>>>(dst, E);
    block_sums_kernel<<<nb1024, 1024, 0, s_csr>>>(M);
    scan_bsum_kernel<<<1, 128, 0, s_csr>>>(nb1024, M, E);
    scan_block_kernel<<<nb1024, 1024, 0, s_csr>>>(M);
    scatter_kernel<<<(E + 255) / 256, 256, 0, s_csr>>>(src, dst, E);
    cudaEventRecord(ev_join, s_csr);

    // ---- main stream: stage 1 GEMM runs concurrently with CSR build ----
    gemm_tc<128, 0, 128, 1><<<dim3(MB, 1), 256, SMEM_BYTES>>>(
        x, nullptr, W_pool, nullptr, b_pool, nullptr, (__half*)pm16, M);

    // ---- join, then gather ----
    cudaStreamWaitEvent(0, ev_join, 0);
    gather_max_kernel<<<(M * 32 + 255) / 256, 256>>>(M);

    // stage 3: h1 = relu(x @ W_self + neigh @ W_neigh + b_sage)
    gemm_tc<128, 128, 256, 0><<<dim3(MB, 2), 256, SMEM_BYTES>>>(
        x, (const float*)pn, W_self, W_neigh, b_sage, (float*)ph1, nullptr, M);

    // stage 4/5: MLP
    gemm_tc<256, 0, 256, 0><<<dim3(MB, 2), 256, SMEM_BYTES>>>(
        (const float*)ph1, nullptr, W1, nullptr, b1, (float*)ph2, nullptr, M);
    gemm_tc<256, 0, 256, 0><<<dim3(MB, 2), 256, SMEM_BYTES>>>(
        (const float*)ph2, nullptr, W2, nullptr, b2, (float*)ph3, nullptr, M);

    // stage 6: chunked per-graph softmax denominator -> final = 1/zsum
    softmax_partial_kernel<<<G * SMX_C, HIDD>>>();
    softmax_combine_kernel<<<G, HIDD>>>();

    // stage 7: out = final @ Wr + br
    readout_kernel<<<(G * 2 + 255) / 256, 256>>>(Wr, br, out, G);
}

// round 14
// speedup vs baseline: 1.2292x; 1.0591x over previous
#include <cuda_runtime.h>
#include <cuda_bf16.h>
#include <cuda_fp16.h>
#include <float.h>

#define NN   100000
#define NE   1600000
#define IND  128
#define HIDD 256
#define NG   256
#define SMX_C 8

// ---------------- static device scratch (allocation-free rule) ----------------
__device__ __half g_m16[NN * IND];     // relu(x @ W_pool + b_pool), fp16
__device__ float g_neigh[NN * IND];    // segment_max over in-edges
__device__ float g_h1[NN * HIDD];
__device__ float g_h2[NN * HIDD];
__device__ float g_h3[NN * HIDD];
__device__ float g_final[NG * HIDD];   // 1/zsum per (graph, feature)
__device__ int   g_start[NG + 1];      // node range per graph (graph_id sorted)

// CSR scratch
__device__ int g_deg[NN];
__device__ int g_cursor[NN];
__device__ int g_off[NN + 1];
__device__ int g_esrc[NE];
__device__ int g_bsum[128];

// softmax partials
__device__ float g_pmax[NG * SMX_C * HIDD];
__device__ float g_psum[NG * SMX_C * HIDD];

// ---------------- FFMA-pipe exp (no MUFU): exp(x), x <= 0 -------------------
__device__ __forceinline__ float fast_exp(float x) {
    float t = x * 1.4426950408889634f;
    t = fmaxf(t, -126.0f);
    float fi = floorf(t);
    float f  = t - fi;
    float p;
    p = fmaf(f, 1.5252733e-5f, 1.5403530e-4f);
    p = fmaf(f, p, 1.3333558e-3f);
    p = fmaf(f, p, 9.6181291e-3f);
    p = fmaf(f, p, 5.5504109e-2f);
    p = fmaf(f, p, 2.4022651e-1f);
    p = fmaf(f, p, 6.9314718e-1f);
    p = fmaf(f, p, 1.0f);
    int ei = (int)fi;
    float sc = __int_as_float((ei + 127) << 23);
    return p * sc;
}

// ---------------- graph ranges: gid sorted -> binary search ----------------
__global__ void find_starts_kernel(const int* __restrict__ gid, int n, int G) {
    int g = blockIdx.x * blockDim.x + threadIdx.x;
    if (g > G) return;
    int lo = 0, hi = n;
    while (lo < hi) {
        int mid = (lo + hi) >> 1;
        if (gid[mid] < g) lo = mid + 1; else hi = mid;
    }
    g_start[g] = lo;
}

// ---------------- CSR build ----------------
__global__ void zero_deg_kernel(int n) {
    int i = blockIdx.x * blockDim.x + threadIdx.x;
    if (i < n) g_deg[i] = 0;
}
__global__ void hist_kernel(const int* __restrict__ dst, int ne) {
    int e = blockIdx.x * blockDim.x + threadIdx.x;
    if (e < ne) atomicAdd(&g_deg[dst[e]], 1);
}
__global__ void block_sums_kernel(int n) {
    __shared__ int sh[1024];
    int i = blockIdx.x * 1024 + threadIdx.x;
    sh[threadIdx.x] = (i < n) ? g_deg[i] : 0;
    __syncthreads();
    for (int s = 512; s > 0; s >>= 1) {
        if (threadIdx.x < s) sh[threadIdx.x] += sh[threadIdx.x + s];
        __syncthreads();
    }
    if (threadIdx.x == 0) g_bsum[blockIdx.x] = sh[0];
}
__global__ void scan_bsum_kernel(int nb, int n, int ne) {
    __shared__ int sh[128];
    int t = threadIdx.x;
    sh[t] = (t < nb) ? g_bsum[t] : 0;
    __syncthreads();
    for (int d = 1; d < 128; d <<= 1) {
        int v = (t >= d) ? sh[t - d] : 0;
        __syncthreads();
        sh[t] += v;
        __syncthreads();
    }
    if (t < nb) g_bsum[t] = (t == 0) ? 0 : sh[t - 1];
    if (t == 0) g_off[n] = ne;
}
__global__ void scan_block_kernel(int n) {
    __shared__ int sh[1024];
    int t = threadIdx.x;
    int i = blockIdx.x * 1024 + t;
    int v = (i < n) ? g_deg[i] : 0;
    sh[t] = v;
    __syncthreads();
    for (int d = 1; d < 1024; d <<= 1) {
        int u = (t >= d) ? sh[t - d] : 0;
        __syncthreads();
        sh[t] += u;
        __syncthreads();
    }
    if (i < n) {
        int off = g_bsum[blockIdx.x] + sh[t] - v;
        g_off[i] = off;
        g_cursor[i] = off;
    }
}
__global__ void scatter_kernel(const int* __restrict__ src, const int* __restrict__ dst, int ne) {
    int e = blockIdx.x * blockDim.x + threadIdx.x;
    if (e < ne) {
        int pos = atomicAdd(&g_cursor[dst[e]], 1);
        g_esrc[pos] = src[e];
    }
}

// ---------------- gather max: warp per dst node, fp16 source ----------------
__global__ void gather_max_kernel(int n) {
    int warp = (blockIdx.x * blockDim.x + threadIdx.x) >> 5;
    if (warp >= n) return;
    int lane = threadIdx.x & 31;
    int c = lane * 4;
    int beg = g_off[warp], end = g_off[warp + 1];
    __half2 z = __floats2half2_rn(0.f, 0.f);
    __half2 a01 = z, a23 = z;
    int j = beg;
    for (; j + 2 <= end; j += 2) {
        int s0 = __ldg(&g_esrc[j]);
        int s1 = __ldg(&g_esrc[j + 1]);
        uint2 w0 = *reinterpret_cast<const uint2*>(&g_m16[s0 * IND + c]);
        uint2 w1 = *reinterpret_cast<const uint2*>(&g_m16[s1 * IND + c]);
        a01 = __hmax2(a01, __hmax2(*(__half2*)&w0.x, *(__half2*)&w1.x));
        a23 = __hmax2(a23, __hmax2(*(__half2*)&w0.y, *(__half2*)&w1.y));
    }
    if (j < end) {
        int s0 = __ldg(&g_esrc[j]);
        uint2 w0 = *reinterpret_cast<const uint2*>(&g_m16[s0 * IND + c]);
        a01 = __hmax2(a01, *(__half2*)&w0.x);
        a23 = __hmax2(a23, *(__half2*)&w0.y);
    }
    float2 f01 = __half22float2(a01);
    float2 f23 = __half22float2(a23);
    *reinterpret_cast<float4*>(&g_neigh[warp * IND + c]) =
        make_float4(f01.x, f01.y, f23.x, f23.y);
}

// ---------------- bf16-split tensor-core GEMM: ldmatrix + double-buffer -----
__device__ __forceinline__ void cvt_hl(float x, unsigned short& h, unsigned short& l) {
    __nv_bfloat16 bh = __float2bfloat16(x);
    __nv_bfloat16 bl = __float2bfloat16(x - __bfloat162float(bh));
    h = __bfloat16_as_ushort(bh);
    l = __bfloat16_as_ushort(bl);
}

__device__ __forceinline__ void mma16816(float* d, const unsigned* a, const unsigned* b) {
    asm volatile("mma.sync.aligned.m16n8k16.row.col.f32.bf16.bf16.f32 "
                 "{%0,%1,%2,%3}, {%4,%5,%6,%7}, {%8,%9}, {%0,%1,%2,%3};"
                 : "+f"(d[0]), "+f"(d[1]), "+f"(d[2]), "+f"(d[3])
                 : "r"(a[0]), "r"(a[1]), "r"(a[2]), "r"(a[3]),
                   "r"(b[0]), "r"(b[1]));
}
__device__ __forceinline__ void ldsm_x4(unsigned* r, unsigned addr) {
    asm volatile("ldmatrix.sync.aligned.m8n8.x4.shared.b16 {%0,%1,%2,%3}, [%4];"
                 : "=r"(r[0]), "=r"(r[1]), "=r"(r[2]), "=r"(r[3]) : "r"(addr));
}

// smem per buffer: A_hi[5120] A_lo[5120] B_hi[5120] B_lo[5120] shorts, rows pad 40.
template<int K1, int K2, int N, int OUTH>
__global__ __launch_bounds__(256, 2)
void gemm_tc(const float* __restrict__ A1, const float* __restrict__ A2,
             const float* __restrict__ B1, const float* __restrict__ B2,
             const float* __restrict__ bias, float* __restrict__ C,
             __half* __restrict__ Ch, int M)
{
    constexpr int KT = K1 + K2;
    constexpr int T  = KT / 32;
    constexpr int PLANE = 5120;         // shorts
    constexpr int STG   = 4 * PLANE;    // shorts per buffer

    extern __shared__ unsigned short sm[];

    const int tid     = threadIdx.x;
    const int rowbase = blockIdx.x * 128;
    const int colbase = blockIdx.y * 128;

    const int lane = tid & 31;
    const int wid  = tid >> 5;
    const int wm   = (wid & 3) * 32;
    const int wn   = (wid >> 2) * 64;
    const int fr   = lane >> 2;
    const int fc   = (lane & 3) * 2;

    const int a_row = tid >> 1;
    const int a_k0  = (tid & 1) * 16;
    const int a_grow = rowbase + a_row;
    const bool a_ok  = a_grow < M;
    const int b_n   = tid & 127;
    const int b_kqb = tid >> 7;

    // ldmatrix per-lane byte offsets within a plane
    const unsigned smem_u32 = (unsigned)__cvta_generic_to_shared(sm);
    const unsigned a_base = smem_u32 +
        (((wm + (lane & 15)) * 40 + ((lane >> 4) << 3)) << 1);
    const unsigned b_base = smem_u32 + (2 * PLANE << 1) +
        (((wn + (lane & 7) + ((lane >> 4) << 3)) * 40 + (((lane >> 3) & 1) << 3)) << 1);

    float acc[2][8][4];
#pragma unroll
    for (int mt = 0; mt < 2; ++mt)
#pragma unroll
        for (int nt = 0; nt < 8; ++nt)
#pragma unroll
            for (int q = 0; q < 4; ++q) acc[mt][nt][q] = 0.f;

    float4 pa[4];
    float  pb[4][4];

    auto loadTile = [&](int t) {
        const int kc = t * 32;
        const float* ap;
        if constexpr (K2 == 0) {
            ap = A1 + (size_t)a_grow * K1 + kc + a_k0;
        } else {
            ap = (kc < K1) ? A1 + (size_t)a_grow * K1 + kc + a_k0
                           : A2 + (size_t)a_grow * K2 + (kc - K1) + a_k0;
        }
#pragma unroll
        for (int i = 0; i < 4; ++i)
            pa[i] = a_ok ? *reinterpret_cast<const float4*>(ap + i * 4)
                         : make_float4(0.f, 0.f, 0.f, 0.f);
#pragma unroll
        for (int it = 0; it < 4; ++it) {
            int kq = it * 2 + b_kqb;
            int kg = kc + kq * 4;
            const float* bp;
            if constexpr (K2 == 0) {
                bp = B1 + (size_t)kg * N + colbase + b_n;
            } else {
                bp = (kg < K1) ? B1 + (size_t)kg * N + colbase + b_n
                               : B2 + (size_t)(kg - K1) * N + colbase + b_n;
            }
#pragma unroll
            for (int i = 0; i < 4; ++i) pb[it][i] = bp[(size_t)i * N];
        }
    };

    auto storeTile = [&](int buf) {
        unsigned short* Ah = sm + buf * STG;
        unsigned short* Al = Ah + PLANE;
        unsigned short* Bh = Ah + 2 * PLANE;
        unsigned short* Bl = Ah + 3 * PLANE;
#pragma unroll
        for (int i = 0; i < 4; ++i) {
            unsigned short h[4], l[4];
            cvt_hl(pa[i].x, h[0], l[0]); cvt_hl(pa[i].y, h[1], l[1]);
            cvt_hl(pa[i].z, h[2], l[2]); cvt_hl(pa[i].w, h[3], l[3]);
            uint2 hw, lw;
            hw.x = ((unsigned)h[1] << 16) | h[0];
            hw.y = ((unsigned)h[3] << 16) | h[2];
            lw.x = ((unsigned)l[1] << 16) | l[0];
            lw.y = ((unsigned)l[3] << 16) | l[2];
            *reinterpret_cast<uint2*>(&Ah[a_row * 40 + a_k0 + i * 4]) = hw;
            *reinterpret_cast<uint2*>(&Al[a_row * 40 + a_k0 + i * 4]) = lw;
        }
#pragma unroll
        for (int it = 0; it < 4; ++it) {
            int kq = it * 2 + b_kqb;
            unsigned short h[4], l[4];
#pragma unroll
            for (int i = 0; i < 4; ++i) cvt_hl(pb[it][i], h[i], l[i]);
            uint2 hw, lw;
            hw.x = ((unsigned)h[1] << 16) | h[0];
            hw.y = ((unsigned)h[3] << 16) | h[2];
            lw.x = ((unsigned)l[1] << 16) | l[0];
            lw.y = ((unsigned)l[3] << 16) | l[2];
            *reinterpret_cast<uint2*>(&Bh[b_n * 40 + kq * 4]) = hw;
            *reinterpret_cast<uint2*>(&Bl[b_n * 40 + kq * 4]) = lw;
        }
    };

    loadTile(0);
    storeTile(0);
    __syncthreads();

#pragma unroll 1
    for (int t = 0; t < T; ++t) {
        if (t + 1 < T) loadTile(t + 1);

        const unsigned bufoff = (unsigned)((t & 1) * STG) << 1;
        const unsigned aH = a_base + bufoff;                 // A hi plane
        const unsigned aL = aH + (PLANE << 1);
        const unsigned bH = b_base + bufoff;                 // B hi plane
        const unsigned bL = bH + (PLANE << 1);

#pragma unroll
        for (int kk = 0; kk < 32; kk += 16) {
            const unsigned kkb = kk << 1;
            unsigned ah[2][4], al[2][4];
#pragma unroll
            for (int mt = 0; mt < 2; ++mt) {
                ldsm_x4(ah[mt], aH + mt * 1280 + kkb);
                ldsm_x4(al[mt], aL + mt * 1280 + kkb);
            }
            // B in two p-group halves to cap register pressure
#pragma unroll
            for (int ph = 0; ph < 2; ++ph) {
                unsigned bh[2][4], bl[2][4];
#pragma unroll
                for (int pp = 0; pp < 2; ++pp) {
                    int p = ph * 2 + pp;
                    ldsm_x4(bh[pp], bH + p * 1280 + kkb);
                    ldsm_x4(bl[pp], bL + p * 1280 + kkb);
                }
#pragma unroll
                for (int pp = 0; pp < 2; ++pp) {
#pragma unroll
                    for (int sub = 0; sub < 2; ++sub) {
                        int nt = (ph * 2 + pp) * 2 + sub;
#pragma unroll
                        for (int mt = 0; mt < 2; ++mt) {
                            mma16816(acc[mt][nt], ah[mt], &bh[pp][sub * 2]);
                            mma16816(acc[mt][nt], ah[mt], &bl[pp][sub * 2]);
                            mma16816(acc[mt][nt], al[mt], &bh[pp][sub * 2]);
                        }
                    }
                }
            }
        }

        if (t + 1 < T) storeTile((t + 1) & 1);
        __syncthreads();
    }

    // ---- epilogue: bias + relu ----
#pragma unroll
    for (int nt = 0; nt < 8; ++nt) {
        int cb = colbase + wn + nt * 8 + fc;
        float2 bi = *reinterpret_cast<const float2*>(&bias[cb]);
#pragma unroll
        for (int mt = 0; mt < 2; ++mt) {
            int r0 = rowbase + wm + mt * 16 + fr;
#pragma unroll
            for (int half = 0; half < 2; ++half) {
                int r = r0 + half * 8;
                if (r < M) {
                    float vx = fmaxf(acc[mt][nt][half * 2 + 0] + bi.x, 0.f);
                    float vy = fmaxf(acc[mt][nt][half * 2 + 1] + bi.y, 0.f);
                    if constexpr (OUTH) {
                        *reinterpret_cast<__half2*>(&Ch[(size_t)r * N + cb]) =
                            __floats2half2_rn(vx, vy);
                    } else {
                        *reinterpret_cast<float2*>(&C[(size_t)r * N + cb]) =
                            make_float2(vx, vy);
                    }
                }
            }
        }
    }
}

// ---------------- chunked per-graph softmax denominator (FFMA exp) ----------
__global__ void softmax_partial_kernel()
{
    int b = blockIdx.x;
    int g = b >> 3, c = b & (SMX_C - 1);
    int s = g_start[g], e = g_start[g + 1];
    int len = e - s;
    int chunk = (len + SMX_C - 1) >> 3;
    int cs = s + c * chunk;
    int ce = min(cs + chunk, e);
    int f = threadIdx.x;
    const float* __restrict__ h = g_h3;

    float mx0 = -FLT_MAX, mx1 = -FLT_MAX;
    float s0 = 0.f, s1 = 0.f;
    int i = cs;
    for (; i + 2 <= ce; i += 2) {
        float v0 = h[(size_t)(i + 0) * HIDD + f];
        float v1 = h[(size_t)(i + 1) * HIDD + f];
        if (v0 > mx0) { s0 *= fast_exp(mx0 - v0); mx0 = v0; }
        s0 += fast_exp(v0 - mx0);
        if (v1 > mx1) { s1 *= fast_exp(mx1 - v1); mx1 = v1; }
        s1 += fast_exp(v1 - mx1);
    }
    for (; i < ce; ++i) {
        float v = h[(size_t)i * HIDD + f];
        if (v > mx0) { s0 *= fast_exp(mx0 - v); mx0 = v; }
        s0 += fast_exp(v - mx0);
    }
    float mx, sm;
    if (cs >= ce) { mx = -FLT_MAX; sm = 0.f; }
    else {
        mx = fmaxf(mx0, mx1);
        sm = s0 * fast_exp(mx0 - mx) + ((s1 > 0.f) ? s1 * fast_exp(mx1 - mx) : 0.f);
    }
    g_pmax[(size_t)b * HIDD + f] = mx;
    g_psum[(size_t)b * HIDD + f] = sm;
}

__global__ void softmax_combine_kernel()
{
    int g = blockIdx.x;
    int f = threadIdx.x;
    float Mx = -FLT_MAX;
#pragma unroll
    for (int c = 0; c < SMX_C; ++c)
        Mx = fmaxf(Mx, g_pmax[(size_t)(g * SMX_C + c) * HIDD + f]);
    float S = 0.f;
#pragma unroll
    for (int c = 0; c < SMX_C; ++c) {
        float pm = g_pmax[(size_t)(g * SMX_C + c) * HIDD + f];
        float ps = g_psum[(size_t)(g * SMX_C + c) * HIDD + f];
        if (ps > 0.f) S += ps * fast_exp(pm - Mx);
    }
    g_final[g * HIDD + f] = (g_start[g + 1] > g_start[g]) ? (1.0f / S) : 0.f;
}

// ---------------- tiny readout: out = final @ Wr + br ----------------
__global__ void readout_kernel(const float* __restrict__ Wr, const float* __restrict__ br,
                               float* __restrict__ out, int ngr)
{
    int t = blockIdx.x * blockDim.x + threadIdx.x;
    if (t < ngr * 2) {
        int g = t >> 1, o = t & 1;
        float acc = br[o];
        const float* fr = &g_final[g * HIDD];
#pragma unroll 8
        for (int f = 0; f < HIDD; ++f) acc = fmaf(fr[f], Wr[f * 2 + o], acc);
        out[t] = acc;
    }
}

// ---------------- launch ----------------
extern "C" void kernel_launch(void* const* d_in, const int* in_sizes, int n_in,
                              void* d_out, int out_size)
{
    const float* x       = (const float*)d_in[0];
    const float* W_pool  = (const float*)d_in[1];
    const float* b_pool  = (const float*)d_in[2];
    const float* W_self  = (const float*)d_in[3];
    const float* W_neigh = (const float*)d_in[4];
    const float* b_sage  = (const float*)d_in[5];
    const float* W1      = (const float*)d_in[6];
    const float* b1      = (const float*)d_in[7];
    const float* W2      = (const float*)d_in[8];
    const float* b2      = (const float*)d_in[9];
    const float* Wr      = (const float*)d_in[10];
    const float* br      = (const float*)d_in[11];
    const int*   src     = (const int*)d_in[12];
    const int*   dst     = (const int*)d_in[13];
    const int*   gid     = (const int*)d_in[14];
    float*       out     = (float*)d_out;

    const int M = in_sizes[0] / IND;   // 100000
    const int E = in_sizes[12];        // 1600000
    const int G = out_size / 2;        // 256

    const int SMEM_BYTES = 2 * 20480 * 2;   // 2 buffers x 20480 shorts = 80 KB

    cudaFuncSetAttribute((const void*)gemm_tc<128, 0, 128, 1>,
                         cudaFuncAttributeMaxDynamicSharedMemorySize, SMEM_BYTES);
    cudaFuncSetAttribute((const void*)gemm_tc<128, 128, 256, 0>,
                         cudaFuncAttributeMaxDynamicSharedMemorySize, SMEM_BYTES);
    cudaFuncSetAttribute((const void*)gemm_tc<256, 0, 256, 0>,
                         cudaFuncAttributeMaxDynamicSharedMemorySize, SMEM_BYTES);

    // side stream + events (created once, outside any graph capture)
    static cudaStream_t s_csr = nullptr;
    static cudaEvent_t  ev_fork = nullptr, ev_join = nullptr;
    if (s_csr == nullptr) {
        cudaStreamCreateWithFlags(&s_csr, cudaStreamNonBlocking);
        cudaEventCreateWithFlags(&ev_fork, cudaEventDisableTiming);
        cudaEventCreateWithFlags(&ev_join, cudaEventDisableTiming);
    }

    void *pm16, *pn, *ph1, *ph2, *ph3;
    cudaGetSymbolAddress(&pm16, g_m16);
    cudaGetSymbolAddress(&pn,  g_neigh);
    cudaGetSymbolAddress(&ph1, g_h1);
    cudaGetSymbolAddress(&ph2, g_h2);
    cudaGetSymbolAddress(&ph3, g_h3);

    const int nb1024 = (M + 1023) / 1024;
    const int MB = (M + 127) / 128;

    // ---- fork: CSR build + graph ranges on side stream ----
    cudaEventRecord(ev_fork, 0);
    cudaStreamWaitEvent(s_csr, ev_fork, 0);
    find_starts_kernel<<<1, 512, 0, s_csr>>>(gid, M, G);
    zero_deg_kernel<<<(M + 255) / 256, 256, 0, s_csr>>>(M);
    hist_kernel<<<(E + 255) / 256, 256, 0, s_csr>>>(dst, E);
    block_sums_kernel<<<nb1024, 1024, 0, s_csr>>>(M);
    scan_bsum_kernel<<<1, 128, 0, s_csr>>>(nb1024, M, E);
    scan_block_kernel<<<nb1024, 1024, 0, s_csr>>>(M);
    scatter_kernel<<<(E + 255) / 256, 256, 0, s_csr>>>(src, dst, E);
    cudaEventRecord(ev_join, s_csr);

    // ---- main stream: stage 1 GEMM runs concurrently with CSR build ----
    gemm_tc<128, 0, 128, 1><<<dim3(MB, 1), 256, SMEM_BYTES>>>(
        x, nullptr, W_pool, nullptr, b_pool, nullptr, (__half*)pm16, M);

    // ---- join, then gather ----
    cudaStreamWaitEvent(0, ev_join, 0);
    gather_max_kernel<<<(M * 32 + 255) / 256, 256>>>(M);

    // stage 3: h1 = relu(x @ W_self + neigh @ W_neigh + b_sage)
    gemm_tc<128, 128, 256, 0><<<dim3(MB, 2), 256, SMEM_BYTES>>>(
        x, (const float*)pn, W_self, W_neigh, b_sage, (float*)ph1, nullptr, M);

    // stage 4/5: MLP
    gemm_tc<256, 0, 256, 0><<<dim3(MB, 2), 256, SMEM_BYTES>>>(
        (const float*)ph1, nullptr, W1, nullptr, b1, (float*)ph2, nullptr, M);
    gemm_tc<256, 0, 256, 0><<<dim3(MB, 2), 256, SMEM_BYTES>>>(
        (const float*)ph2, nullptr, W2, nullptr, b2, (float*)ph3, nullptr, M);

    // stage 6: chunked per-graph softmax denominator -> final = 1/zsum
    softmax_partial_kernel<<<G * SMX_C, HIDD>>>();
    softmax_combine_kernel<<<G, HIDD>>>();

    // stage 7: out = final @ Wr + br
    readout_kernel<<<(G * 2 + 255) / 256, 256>>>(Wr, br, out, G);
}